// round 1
// baseline (speedup 1.0000x reference)
#include <cuda_runtime.h>
#include <stdint.h>
#include <math.h>

#define NN 8192
#define EE 262144
#define DI 256
#define DL 128

#define H_OFF (NN*DL)
#define LOSS_OFF (NN*DL + NN*DI)

// ------------------------- scratch (__device__ globals) -------------------------
__device__ float g_xl_e[NN*DL];
__device__ float g_xr_e[NN*DL];
__device__ float g_xl_p[NN*DL];
__device__ float g_xr_p[NN*DL];
__device__ float g_xl_n[NN*DL];
__device__ float g_xr_n[NN*DL];
__device__ float g_xl_d[NN*DI];
__device__ float g_xr_d[NN*DI];
__device__ float g_g1[NN*DL];
__device__ float g_g2[NN*DL];
__device__ float g_h0[NN*DL];
__device__ float g_h1[NN*DL];
__device__ float g_h2[NN*DL];
__device__ float g_logit[EE];
__device__ unsigned g_menc[NN];
__device__ float g_m[NN];
__device__ float g_denom[NN];
__device__ float g_Wlm[DI*DL];
__device__ float g_Wrm[DI*DL];
__device__ int g_perm[NN];
__device__ int g_ptmp[NN];
__device__ unsigned g_bits[NN];
__device__ float g_keep[DI];
__device__ unsigned g_keys[6];     // [0:2]=sub1 [2:4]=sub2 [4:6]=k2
__device__ float g_bnsum[DL];
__device__ float g_bnsq[DL];
__device__ float g_acc[2];         // [0]=rec_sum [1]=ctr_sum

// ------------------------- threefry2x32-20 -------------------------
__device__ __forceinline__ void tfry(uint32_t k0, uint32_t k1, uint32_t x0, uint32_t x1,
                                     uint32_t* o0, uint32_t* o1) {
    uint32_t ks2 = k0 ^ k1 ^ 0x1BD11BDAu;
    x0 += k0; x1 += k1;
#define RR(r) { x0 += x1; x1 = (x1 << (r)) | (x1 >> (32 - (r))); x1 ^= x0; }
    RR(13) RR(15) RR(26) RR(6)  x0 += k1;  x1 += ks2 + 1u;
    RR(17) RR(29) RR(16) RR(24) x0 += ks2; x1 += k0 + 2u;
    RR(13) RR(15) RR(26) RR(6)  x0 += k0;  x1 += k1 + 3u;
    RR(17) RR(29) RR(16) RR(24) x0 += k1;  x1 += ks2 + 4u;
    RR(13) RR(15) RR(26) RR(6)  x0 += ks2; x1 += k0 + 5u;
#undef RR
    *o0 = x0; *o1 = x1;
}

__global__ void k_init() {
    if (threadIdx.x == 0) {
        // kp = key(42) -> data (0, 42). split(kp): counts [0,1,2,3], lanes (0,2),(1,3)
        uint32_t a0, a1, b0, b1;
        tfry(0u, 42u, 0u, 2u, &a0, &a1);
        tfry(0u, 42u, 1u, 3u, &b0, &b1);
        uint32_t k1_0 = a0, k1_1 = b0;   // row 0
        uint32_t k2_0 = a1, k2_1 = b1;   // row 1
        // shuffle round 1: keyA, sub1 = split(k1)
        uint32_t c0, c1, d0, d1;
        tfry(k1_0, k1_1, 0u, 2u, &c0, &c1);
        tfry(k1_0, k1_1, 1u, 3u, &d0, &d1);
        uint32_t kA0 = c0, kA1 = d0;
        g_keys[0] = c1; g_keys[1] = d1;        // sub1
        // round 2: keyB, sub2 = split(keyA)
        uint32_t e0, e1, f0, f1;
        tfry(kA0, kA1, 0u, 2u, &e0, &e1);
        tfry(kA0, kA1, 1u, 3u, &f0, &f1);
        g_keys[2] = e1; g_keys[3] = f1;        // sub2
        g_keys[4] = k2_0; g_keys[5] = k2_1;    // k2 (for uniform mask)
        g_acc[0] = 0.f; g_acc[1] = 0.f;
    }
}

__global__ void k_bits(int which) {
    int i = blockIdx.x * blockDim.x + threadIdx.x;
    if (i >= NN / 2) return;
    uint32_t lo, hi;
    tfry(g_keys[which * 2], g_keys[which * 2 + 1], (uint32_t)i, (uint32_t)(i + NN / 2), &lo, &hi);
    g_bits[i] = lo; g_bits[i + NN / 2] = hi;
}

__global__ void k_rank(const int* __restrict__ pin, int* __restrict__ pout, int use_identity) {
    int i = blockIdx.x * blockDim.x + threadIdx.x;
    if (i >= NN) return;
    unsigned long long ki = (((unsigned long long)g_bits[i]) << 13) | (unsigned)i;
    int rank = 0;
    for (int j = 0; j < NN; j++) {
        unsigned long long kj = (((unsigned long long)g_bits[j]) << 13) | (unsigned)j;
        rank += (kj < ki);
    }
    pout[rank] = use_identity ? i : pin[i];
}

__global__ void k_keep() {
    int i = threadIdx.x;
    if (i >= DI / 2) return;
    uint32_t lo, hi;
    tfry(g_keys[4], g_keys[5], (uint32_t)i, (uint32_t)(i + DI / 2), &lo, &hi);
    float ulo = __uint_as_float((lo >> 9) | 0x3f800000u) - 1.0f;
    float uhi = __uint_as_float((hi >> 9) | 0x3f800000u) - 1.0f;
    g_keep[i] = (ulo >= 0.3f) ? 1.f : 0.f;
    g_keep[i + DI / 2] = (uhi >= 0.3f) ? 1.f : 0.f;
}

__global__ void k_maskw(const float* __restrict__ Wl, const float* __restrict__ Wr) {
    int idx = blockIdx.x * blockDim.x + threadIdx.x;
    if (idx >= DI * DL) return;
    float kmask = g_keep[idx / DL];
    g_Wlm[idx] = kmask * Wl[idx];
    g_Wrm[idx] = kmask * Wr[idx];
}

// ------------------------- GEMM: C[M,D] = A[M,K] @ B[K,D], 64x64 tiles -------------------------
__global__ void k_gemm(const float* __restrict__ A, const float* __restrict__ B,
                       float* __restrict__ C, int K, int D) {
    __shared__ float As[16 * 68];  // As[k][row]
    __shared__ float Bs[16 * 68];  // Bs[k][col]
    int tid = threadIdx.x;
    int tx = tid & 15, ty = tid >> 4;
    int row0 = blockIdx.y * 64, col0 = blockIdx.x * 64;
    float acc[4][4] = {};
    for (int k0 = 0; k0 < K; k0 += 16) {
#pragma unroll
        for (int t = 0; t < 4; t++) {
            int idx = tid + t * 256;
            int ka = idx & 15, r = idx >> 4;
            As[ka * 68 + r] = A[(row0 + r) * K + k0 + ka];
            int c = idx & 63, kb = idx >> 6;
            Bs[kb * 68 + c] = B[(k0 + kb) * D + col0 + c];
        }
        __syncthreads();
#pragma unroll
        for (int kk = 0; kk < 16; kk++) {
            float4 a = *(const float4*)&As[kk * 68 + ty * 4];
            float4 b = *(const float4*)&Bs[kk * 68 + tx * 4];
            acc[0][0] += a.x * b.x; acc[0][1] += a.x * b.y; acc[0][2] += a.x * b.z; acc[0][3] += a.x * b.w;
            acc[1][0] += a.y * b.x; acc[1][1] += a.y * b.y; acc[1][2] += a.y * b.z; acc[1][3] += a.y * b.w;
            acc[2][0] += a.z * b.x; acc[2][1] += a.z * b.y; acc[2][2] += a.z * b.z; acc[2][3] += a.z * b.w;
            acc[3][0] += a.w * b.x; acc[3][1] += a.w * b.y; acc[3][2] += a.w * b.z; acc[3][3] += a.w * b.w;
        }
        __syncthreads();
    }
#pragma unroll
    for (int i = 0; i < 4; i++) {
        float4 o = make_float4(acc[i][0], acc[i][1], acc[i][2], acc[i][3]);
        *(float4*)&C[(row0 + ty * 4 + i) * D + col0 + tx * 4] = o;
    }
}

__global__ void k_gatherperm() {
    int idx = blockIdx.x * blockDim.x + threadIdx.x;
    if (idx >= NN * DL) return;
    int i = idx / DL, d = idx % DL;
    int p = g_perm[i];
    g_xl_n[idx] = g_xl_e[p * DL + d];
    g_xr_n[idx] = g_xr_e[p * DL + d];
}

// ------------------------- GAT edge kernels -------------------------
__device__ __forceinline__ unsigned fenc(float f) {
    unsigned u = __float_as_uint(f);
    return (u & 0x80000000u) ? ~u : (u | 0x80000000u);
}
__device__ __forceinline__ float fdec(unsigned u) {
    return (u & 0x80000000u) ? __uint_as_float(u & 0x7FFFFFFFu) : __uint_as_float(~u);
}

__global__ void k_prep_out(float* __restrict__ out, const float* __restrict__ bias, int D) {
    int idx = blockIdx.x * blockDim.x + threadIdx.x;
    if (idx >= NN * D) return;
    out[idx] = bias[idx % D];
}

__global__ void k_prep_node() {
    int i = blockIdx.x * blockDim.x + threadIdx.x;
    if (i >= NN) return;
    g_menc[i] = fenc(-INFINITY);
    g_denom[i] = 0.f;
}

__global__ void k_logit(const int* __restrict__ src, const int* __restrict__ dst,
                        const float* __restrict__ xl, const float* __restrict__ xr,
                        const float* __restrict__ att, int D) {
    int gt = blockIdx.x * blockDim.x + threadIdx.x;
    int e = gt >> 5, lane = gt & 31;
    if (e >= EE) return;
    int s = src[e], d0 = dst[e];
    float acc = 0.f;
    for (int j = lane; j < D; j += 32) {
        float v = xl[s * D + j] + xr[d0 * D + j];
        v = v > 0.f ? v : 0.2f * v;
        acc += v * att[j];
    }
#pragma unroll
    for (int o = 16; o; o >>= 1) acc += __shfl_down_sync(0xffffffffu, acc, o);
    if (lane == 0) {
        g_logit[e] = acc;
        atomicMax(&g_menc[d0], fenc(acc));
    }
}

__global__ void k_mfix() {
    int i = blockIdx.x * blockDim.x + threadIdx.x;
    if (i >= NN) return;
    float f = fdec(g_menc[i]);
    g_m[i] = isfinite(f) ? f : 0.f;
}

__global__ void k_exp(const int* __restrict__ dst) {
    int e = blockIdx.x * blockDim.x + threadIdx.x;
    if (e >= EE) return;
    int d0 = dst[e];
    float ex = expf(g_logit[e] - g_m[d0]);
    g_logit[e] = ex;
    atomicAdd(&g_denom[d0], ex);
}

__global__ void k_scatter(const int* __restrict__ src, const int* __restrict__ dst,
                          const float* __restrict__ xl, const float* __restrict__ w,
                          float* __restrict__ out, int D) {
    int gt = blockIdx.x * blockDim.x + threadIdx.x;
    int e = gt >> 5, lane = gt & 31;
    if (e >= EE) return;
    int s = src[e], d0 = dst[e];
    float alpha;
    if (lane == 0) alpha = g_logit[e] / (g_denom[d0] + 1e-16f) * w[e];
    alpha = __shfl_sync(0xffffffffu, alpha, 0);
    for (int j = lane; j < D; j += 32)
        atomicAdd(&out[d0 * D + j], alpha * xl[s * D + j]);
}

// ------------------------- BatchNorm + ELU -------------------------
__global__ void k_bnzero() {
    int c = threadIdx.x;
    g_bnsum[c] = 0.f; g_bnsq[c] = 0.f;
}

__global__ void k_bnstats(const float* __restrict__ A) {
    int c = threadIdx.x % DL;
    int part = threadIdx.x / DL;
    int rbase = blockIdx.x * 256 + part * 128;
    float s = 0.f, q = 0.f;
    for (int r = 0; r < 128; r++) {
        float v = A[(rbase + r) * DL + c];
        s += v; q += v * v;
    }
    atomicAdd(&g_bnsum[c], s);
    atomicAdd(&g_bnsq[c], q);
}

__global__ void k_bnapply(const float* __restrict__ A, float* __restrict__ out,
                          const float* __restrict__ gamma, const float* __restrict__ beta) {
    int idx = blockIdx.x * blockDim.x + threadIdx.x;
    if (idx >= NN * DL) return;
    int c = idx & (DL - 1);
    float mu = g_bnsum[c] * (1.f / NN);
    float var = g_bnsq[c] * (1.f / NN) - mu * mu;
    float y = (A[idx] - mu) * rsqrtf(var + 1e-5f) * gamma[c] + beta[c];
    out[idx] = y > 0.f ? y : expm1f(y);
}

__global__ void k_l2(float* __restrict__ A) {
    int gt = blockIdx.x * blockDim.x + threadIdx.x;
    int row = gt >> 5, lane = gt & 31;
    if (row >= NN) return;
    float4* p = (float4*)(A + row * DL);
    float4 v = p[lane];
    float s = v.x * v.x + v.y * v.y + v.z * v.z + v.w * v.w;
#pragma unroll
    for (int o = 16; o; o >>= 1) s += __shfl_xor_sync(0xffffffffu, s, o);
    float inv = 1.f / sqrtf(s);
    v.x *= inv; v.y *= inv; v.z *= inv; v.w *= inv;
    p[lane] = v;
}

// ------------------------- reconstruction loss -------------------------
__global__ void k_rec(const float* __restrict__ x, const float* __restrict__ h) {
    float s = 0.f;
    for (int i = blockIdx.x * blockDim.x + threadIdx.x; i < NN * DI; i += gridDim.x * blockDim.x) {
        float d = x[i] - h[i];
        s += d * d;
    }
#pragma unroll
    for (int o = 16; o; o >>= 1) s += __shfl_down_sync(0xffffffffu, s, o);
    __shared__ float red[8];
    int lane = threadIdx.x & 31, wid = threadIdx.x >> 5;
    if (lane == 0) red[wid] = s;
    __syncthreads();
    if (threadIdx.x == 0) {
        float t = 0.f;
        for (int i = 0; i < 8; i++) t += red[i];
        atomicAdd(&g_acc[0], t);
    }
}

// ------------------------- InfoNCE (logits bounded in [-2,2] -> no online max) -------------------------
#define NCE_SM ((128 * 36 + 128 * 68) * 4)
__global__ void k_nce(const float* __restrict__ q, const float* __restrict__ pk,
                      const float* __restrict__ nk) {
    extern __shared__ float sm[];
    float* qsT = sm;               // [128][36] (rows of q tile, transposed)
    float* nsT = sm + 128 * 36;    // [128][68]
    __shared__ float rowpos[32];
    __shared__ float blksum;
    int tid = threadIdx.x;
    int r0 = blockIdx.x * 32;
#pragma unroll
    for (int t = 0; t < 16; t++) {
        int idx = tid + t * 256;
        int k = idx & 127, r = idx >> 7;
        qsT[k * 36 + r] = q[(r0 + r) * DL + k];
    }
    if (tid == 0) blksum = 0.f;
    __syncthreads();
    if (tid < 32) {
        float p = 0.f;
        for (int k = 0; k < DL; k++) p += qsT[k * 36 + tid] * pk[(r0 + tid) * DL + k];
        rowpos[tid] = 2.f * p;
    }
    int tx = tid & 15, ty = tid >> 4;
    float se0 = 0.f, se1 = 0.f;
    for (int c0 = 0; c0 < NN; c0 += 64) {
        __syncthreads();
#pragma unroll
        for (int t = 0; t < 32; t++) {
            int idx = tid + t * 256;
            int k = idx & 127, c = idx >> 7;
            nsT[k * 68 + c] = nk[(c0 + c) * DL + k];
        }
        __syncthreads();
        float v00 = 0, v01 = 0, v02 = 0, v03 = 0, v10 = 0, v11 = 0, v12 = 0, v13 = 0;
#pragma unroll 4
        for (int kk = 0; kk < 128; kk++) {
            float2 a = *(const float2*)&qsT[kk * 36 + ty * 2];
            float4 b = *(const float4*)&nsT[kk * 68 + tx * 4];
            v00 += a.x * b.x; v01 += a.x * b.y; v02 += a.x * b.z; v03 += a.x * b.w;
            v10 += a.y * b.x; v11 += a.y * b.y; v12 += a.y * b.z; v13 += a.y * b.w;
        }
        se0 += expf(2.f * v00) + expf(2.f * v01) + expf(2.f * v02) + expf(2.f * v03);
        se1 += expf(2.f * v10) + expf(2.f * v11) + expf(2.f * v12) + expf(2.f * v13);
    }
#pragma unroll
    for (int o = 8; o; o >>= 1) {
        se0 += __shfl_xor_sync(0xffffffffu, se0, o);
        se1 += __shfl_xor_sync(0xffffffffu, se1, o);
    }
    if (tx == 0) {
        int r = ty * 2;
        float t0 = logf(se0 + expf(rowpos[r])) - rowpos[r];
        float t1 = logf(se1 + expf(rowpos[r + 1])) - rowpos[r + 1];
        atomicAdd(&blksum, t0 + t1);
    }
    __syncthreads();
    if (tid == 0) atomicAdd(&g_acc[1], blksum);
}

__global__ void k_final(float* __restrict__ loss) {
    loss[0] = g_acc[0] * (1.f / (float)(NN * DI)) + 0.2f * (g_acc[1] * (1.f / (float)NN));
}

// ------------------------- host orchestration -------------------------
static void* sym_addr_helper(const void* symbol) {
    void* p = nullptr;
    cudaGetSymbolAddress(&p, symbol);
    return p;
}
#define SYM(x) ((float*)sym_addr_helper((const void*)&x))
#define SYMI(x) ((int*)sym_addr_helper((const void*)&x))

static void run_gat(const int* src, const int* dst, const float* w,
                    const float* xl, const float* xr, const float* att,
                    const float* bias, float* out, int D) {
    k_prep_out<<<(NN * D) / 256, 256>>>(out, bias, D);
    k_prep_node<<<NN / 256, 256>>>();
    k_logit<<<EE / 8, 256>>>(src, dst, xl, xr, att, D);
    k_mfix<<<NN / 256, 256>>>();
    k_exp<<<EE / 256, 256>>>(dst);
    k_scatter<<<EE / 8, 256>>>(src, dst, xl, w, out, D);
}

static void run_bn(const float* A, float* out, const float* gamma, const float* beta) {
    k_bnzero<<<1, 128>>>();
    k_bnstats<<<32, 256>>>(A);
    k_bnapply<<<(NN * DL) / 256, 256>>>(A, out, gamma, beta);
}

extern "C" void kernel_launch(void* const* d_in, const int* in_sizes, int n_in,
                              void* d_out, int out_size) {
    (void)in_sizes; (void)n_in; (void)out_size;
    const float* x       = (const float*)d_in[0];
    const int*   gsi     = (const int*)d_in[1];
    const int*   gfi     = (const int*)d_in[2];
    const float* w_h     = (const float*)d_in[3];
    const float* w_h_a   = (const float*)d_in[4];
    const float* enc_Wl  = (const float*)d_in[5];
    const float* enc_Wr  = (const float*)d_in[6];
    const float* enc_att = (const float*)d_in[7];
    const float* enc_b   = (const float*)d_in[8];
    const float* dec_Wl  = (const float*)d_in[9];
    const float* dec_Wr  = (const float*)d_in[10];
    const float* dec_att = (const float*)d_in[11];
    const float* dec_b   = (const float*)d_in[12];
    const float* bn_g    = (const float*)d_in[13];
    const float* bn_b    = (const float*)d_in[14];

    float* out  = (float*)d_out;
    float* hi   = out;
    float* h    = out + H_OFF;
    float* loss = out + LOSS_OFF;

    const int* s_src = gsi;
    const int* s_dst = gsi + EE;
    const int* f_src = gfi;
    const int* f_dst = gfi + EE;

    float* xl_e = SYM(g_xl_e); float* xr_e = SYM(g_xr_e);
    float* xl_p = SYM(g_xl_p); float* xr_p = SYM(g_xr_p);
    float* xl_n = SYM(g_xl_n); float* xr_n = SYM(g_xr_n);
    float* xl_d = SYM(g_xl_d); float* xr_d = SYM(g_xr_d);
    float* gg1 = SYM(g_g1);  float* gg2 = SYM(g_g2);
    float* h0 = SYM(g_h0);   float* h1p = SYM(g_h1);  float* h2p = SYM(g_h2);
    float* Wlm = SYM(g_Wlm); float* Wrm = SYM(g_Wrm);
    int* ptmp = SYMI(g_ptmp); int* perm = SYMI(g_perm);

    cudaFuncSetAttribute(k_nce, cudaFuncAttributeMaxDynamicSharedMemorySize, NCE_SM);

    // ---- RNG: permutation (2 stable sort rounds) + feature keep mask ----
    k_init<<<1, 32>>>();
    k_bits<<<16, 256>>>(0);
    k_rank<<<32, 256>>>(nullptr, ptmp, 1);
    k_bits<<<16, 256>>>(1);
    k_rank<<<32, 256>>>(ptmp, perm, 0);
    k_keep<<<1, 128>>>();
    k_maskw<<<(DI * DL) / 256, 256>>>(enc_Wl, enc_Wr);

    // ---- encoder GEMMs ----
    dim3 ge(DL / 64, NN / 64);
    k_gemm<<<ge, 256>>>(x, enc_Wl, xl_e, DI, DL);
    k_gemm<<<ge, 256>>>(x, enc_Wr, xr_e, DI, DL);
    k_gemm<<<ge, 256>>>(x, Wlm, xl_p, DI, DL);
    k_gemm<<<ge, 256>>>(x, Wrm, xr_p, DI, DL);
    k_gatherperm<<<(NN * DL) / 256, 256>>>();

    // ---- GAT calls: hi, g1 (x_p on g_f), g2 (x_n on g_s) ----
    run_gat(s_src, s_dst, w_h, xl_e, xr_e, enc_att, enc_b, hi, DL);
    run_gat(f_src, f_dst, w_h_a, xl_p, xr_p, enc_att, enc_b, gg1, DL);
    run_gat(s_src, s_dst, w_h, xl_n, xr_n, enc_att, enc_b, gg2, DL);

    // ---- decoder ----
    dim3 gd(DI / 64, NN / 64);
    k_gemm<<<gd, 256>>>(hi, dec_Wl, xl_d, DL, DI);
    k_gemm<<<gd, 256>>>(hi, dec_Wr, xr_d, DL, DI);
    run_gat(s_src, s_dst, w_h, xl_d, xr_d, dec_att, dec_b, h, DI);

    // ---- BN + ELU + L2 norm ----
    run_bn(hi, h0, bn_g, bn_b);
    run_bn(gg1, h1p, bn_g, bn_b);
    run_bn(gg2, h2p, bn_g, bn_b);
    k_l2<<<NN / 8, 256>>>(h0);
    k_l2<<<NN / 8, 256>>>(h1p);
    k_l2<<<NN / 8, 256>>>(h2p);

    // ---- losses ----
    k_rec<<<256, 256>>>(x, h);
    k_nce<<<NN / 32, 256, NCE_SM>>>(h0, h1p, h2p);
    k_final<<<1, 1>>>(loss);
}

// round 2
// speedup vs baseline: 1.2565x; 1.2565x over previous
#include <cuda_runtime.h>
#include <cuda_bf16.h>
#include <mma.h>
#include <stdint.h>
#include <math.h>

using namespace nvcuda;

#define NN 8192
#define EE 262144
#define DI 256
#define DL 128

#define H_OFF (NN*DL)
#define LOSS_OFF (NN*DL + NN*DI)

// ------------------------- scratch (__device__ globals) -------------------------
__device__ float g_xl_e[NN*DL];
__device__ float g_xr_e[NN*DL];
__device__ float g_xl_p[NN*DL];
__device__ float g_xr_p[NN*DL];
__device__ float g_xl_n[NN*DL];
__device__ float g_xr_n[NN*DL];
__device__ float g_xl_d[NN*DI];
__device__ float g_xr_d[NN*DI];
__device__ float g_g1[NN*DL];
__device__ float g_g2[NN*DL];
__device__ float g_h0[NN*DL];
__device__ float g_h1[NN*DL];
__device__ float g_h2[NN*DL];
__device__ __nv_bfloat16 g_q16[NN*DL];
__device__ __nv_bfloat16 g_p16[NN*DL];
__device__ __nv_bfloat16 g_n16[NN*DL];
__device__ float g_logit[EE];
__device__ unsigned g_menc[NN];
__device__ float g_m[NN];
__device__ float g_denom[NN];
__device__ float g_Wlm[DI*DL];
__device__ float g_Wrm[DI*DL];
__device__ int g_perm[NN];
__device__ int g_ptmp[NN];
__device__ unsigned g_bits[NN];
__device__ float g_keep[DI];
__device__ unsigned g_keys[6];     // [0:2]=sub1 [2:4]=sub2 [4:6]=k2
__device__ float g_bnsum[DL];
__device__ float g_bnsq[DL];
__device__ float g_acc[2];         // [0]=rec_sum [1]=ctr_sum

// ------------------------- threefry2x32-20 -------------------------
__device__ __forceinline__ void tfry(uint32_t k0, uint32_t k1, uint32_t x0, uint32_t x1,
                                     uint32_t* o0, uint32_t* o1) {
    uint32_t ks2 = k0 ^ k1 ^ 0x1BD11BDAu;
    x0 += k0; x1 += k1;
#define RR(r) { x0 += x1; x1 = (x1 << (r)) | (x1 >> (32 - (r))); x1 ^= x0; }
    RR(13) RR(15) RR(26) RR(6)  x0 += k1;  x1 += ks2 + 1u;
    RR(17) RR(29) RR(16) RR(24) x0 += ks2; x1 += k0 + 2u;
    RR(13) RR(15) RR(26) RR(6)  x0 += k0;  x1 += k1 + 3u;
    RR(17) RR(29) RR(16) RR(24) x0 += k1;  x1 += ks2 + 4u;
    RR(13) RR(15) RR(26) RR(6)  x0 += ks2; x1 += k0 + 5u;
#undef RR
    *o0 = x0; *o1 = x1;
}

__global__ void k_init() {
    if (threadIdx.x == 0) {
        uint32_t a0, a1, b0, b1;
        tfry(0u, 42u, 0u, 2u, &a0, &a1);
        tfry(0u, 42u, 1u, 3u, &b0, &b1);
        uint32_t k1_0 = a0, k1_1 = b0;   // row 0
        uint32_t k2_0 = a1, k2_1 = b1;   // row 1
        uint32_t c0, c1, d0, d1;
        tfry(k1_0, k1_1, 0u, 2u, &c0, &c1);
        tfry(k1_0, k1_1, 1u, 3u, &d0, &d1);
        uint32_t kA0 = c0, kA1 = d0;
        g_keys[0] = c1; g_keys[1] = d1;        // sub1
        uint32_t e0, e1, f0, f1;
        tfry(kA0, kA1, 0u, 2u, &e0, &e1);
        tfry(kA0, kA1, 1u, 3u, &f0, &f1);
        g_keys[2] = e1; g_keys[3] = f1;        // sub2
        g_keys[4] = k2_0; g_keys[5] = k2_1;    // k2
        g_acc[0] = 0.f; g_acc[1] = 0.f;
    }
}

__global__ void k_bits(int which) {
    int i = blockIdx.x * blockDim.x + threadIdx.x;
    if (i >= NN / 2) return;
    uint32_t lo, hi;
    tfry(g_keys[which * 2], g_keys[which * 2 + 1], (uint32_t)i, (uint32_t)(i + NN / 2), &lo, &hi);
    g_bits[i] = lo; g_bits[i + NN / 2] = hi;
}

__global__ void k_rank(const int* __restrict__ pin, int* __restrict__ pout, int use_identity) {
    int i = blockIdx.x * blockDim.x + threadIdx.x;
    if (i >= NN) return;
    unsigned long long ki = (((unsigned long long)g_bits[i]) << 13) | (unsigned)i;
    int rank = 0;
    for (int j = 0; j < NN; j++) {
        unsigned long long kj = (((unsigned long long)g_bits[j]) << 13) | (unsigned)j;
        rank += (kj < ki);
    }
    pout[rank] = use_identity ? i : pin[i];
}

__global__ void k_keep() {
    int i = threadIdx.x;
    if (i >= DI / 2) return;
    uint32_t lo, hi;
    tfry(g_keys[4], g_keys[5], (uint32_t)i, (uint32_t)(i + DI / 2), &lo, &hi);
    float ulo = __uint_as_float((lo >> 9) | 0x3f800000u) - 1.0f;
    float uhi = __uint_as_float((hi >> 9) | 0x3f800000u) - 1.0f;
    g_keep[i] = (ulo >= 0.3f) ? 1.f : 0.f;
    g_keep[i + DI / 2] = (uhi >= 0.3f) ? 1.f : 0.f;
}

__global__ void k_maskw(const float* __restrict__ Wl, const float* __restrict__ Wr) {
    int idx = blockIdx.x * blockDim.x + threadIdx.x;
    if (idx >= DI * DL) return;
    float kmask = g_keep[idx / DL];
    g_Wlm[idx] = kmask * Wl[idx];
    g_Wrm[idx] = kmask * Wr[idx];
}

// ------------------------- GEMM: C[M,D] = A[M,K] @ B[K,D], 64x64 tiles -------------------------
__global__ void k_gemm(const float* __restrict__ A, const float* __restrict__ B,
                       float* __restrict__ C, int K, int D) {
    __shared__ float As[16 * 68];  // As[k][row]
    __shared__ float Bs[16 * 68];  // Bs[k][col]
    int tid = threadIdx.x;
    int tx = tid & 15, ty = tid >> 4;
    int row0 = blockIdx.y * 64, col0 = blockIdx.x * 64;
    float acc[4][4] = {};
    for (int k0 = 0; k0 < K; k0 += 16) {
#pragma unroll
        for (int t = 0; t < 4; t++) {
            int idx = tid + t * 256;
            int ka = idx & 15, r = idx >> 4;
            As[ka * 68 + r] = A[(row0 + r) * K + k0 + ka];
            int c = idx & 63, kb = idx >> 6;
            Bs[kb * 68 + c] = B[(k0 + kb) * D + col0 + c];
        }
        __syncthreads();
#pragma unroll
        for (int kk = 0; kk < 16; kk++) {
            float4 a = *(const float4*)&As[kk * 68 + ty * 4];
            float4 b = *(const float4*)&Bs[kk * 68 + tx * 4];
            acc[0][0] += a.x * b.x; acc[0][1] += a.x * b.y; acc[0][2] += a.x * b.z; acc[0][3] += a.x * b.w;
            acc[1][0] += a.y * b.x; acc[1][1] += a.y * b.y; acc[1][2] += a.y * b.z; acc[1][3] += a.y * b.w;
            acc[2][0] += a.z * b.x; acc[2][1] += a.z * b.y; acc[2][2] += a.z * b.z; acc[2][3] += a.z * b.w;
            acc[3][0] += a.w * b.x; acc[3][1] += a.w * b.y; acc[3][2] += a.w * b.z; acc[3][3] += a.w * b.w;
        }
        __syncthreads();
    }
#pragma unroll
    for (int i = 0; i < 4; i++) {
        float4 o = make_float4(acc[i][0], acc[i][1], acc[i][2], acc[i][3]);
        *(float4*)&C[(row0 + ty * 4 + i) * D + col0 + tx * 4] = o;
    }
}

__global__ void k_gatherperm() {
    int idx = blockIdx.x * blockDim.x + threadIdx.x;
    if (idx >= NN * DL) return;
    int i = idx / DL, d = idx % DL;
    int p = g_perm[i];
    g_xl_n[idx] = g_xl_e[p * DL + d];
    g_xr_n[idx] = g_xr_e[p * DL + d];
}

// ------------------------- GAT edge kernels -------------------------
__device__ __forceinline__ unsigned fenc(float f) {
    unsigned u = __float_as_uint(f);
    return (u & 0x80000000u) ? ~u : (u | 0x80000000u);
}
__device__ __forceinline__ float fdec(unsigned u) {
    return (u & 0x80000000u) ? __uint_as_float(u & 0x7FFFFFFFu) : __uint_as_float(~u);
}

__global__ void k_prep_out(float* __restrict__ out, const float* __restrict__ bias, int D) {
    int idx = blockIdx.x * blockDim.x + threadIdx.x;
    if (idx >= NN * D) return;
    out[idx] = bias[idx % D];
}

__global__ void k_prep_node() {
    int i = blockIdx.x * blockDim.x + threadIdx.x;
    if (i >= NN) return;
    g_menc[i] = fenc(-INFINITY);
    g_denom[i] = 0.f;
}

__global__ void k_logit(const int* __restrict__ src, const int* __restrict__ dst,
                        const float* __restrict__ xl, const float* __restrict__ xr,
                        const float* __restrict__ att, int D) {
    int gt = blockIdx.x * blockDim.x + threadIdx.x;
    int e = gt >> 5, lane = gt & 31;
    if (e >= EE) return;
    int s = src[e], d0 = dst[e];
    float acc = 0.f;
    for (int j = lane; j < D; j += 32) {
        float v = xl[s * D + j] + xr[d0 * D + j];
        v = v > 0.f ? v : 0.2f * v;
        acc += v * att[j];
    }
#pragma unroll
    for (int o = 16; o; o >>= 1) acc += __shfl_down_sync(0xffffffffu, acc, o);
    if (lane == 0) {
        g_logit[e] = acc;
        atomicMax(&g_menc[d0], fenc(acc));
    }
}

__global__ void k_mfix() {
    int i = blockIdx.x * blockDim.x + threadIdx.x;
    if (i >= NN) return;
    float f = fdec(g_menc[i]);
    g_m[i] = isfinite(f) ? f : 0.f;
}

__global__ void k_exp(const int* __restrict__ dst) {
    int e = blockIdx.x * blockDim.x + threadIdx.x;
    if (e >= EE) return;
    int d0 = dst[e];
    float ex = expf(g_logit[e] - g_m[d0]);
    g_logit[e] = ex;
    atomicAdd(&g_denom[d0], ex);
}

__global__ void k_scatter(const int* __restrict__ src, const int* __restrict__ dst,
                          const float* __restrict__ xl, const float* __restrict__ w,
                          float* __restrict__ out, int D) {
    int gt = blockIdx.x * blockDim.x + threadIdx.x;
    int e = gt >> 5, lane = gt & 31;
    if (e >= EE) return;
    int s = src[e], d0 = dst[e];
    float alpha;
    if (lane == 0) alpha = g_logit[e] / (g_denom[d0] + 1e-16f) * w[e];
    alpha = __shfl_sync(0xffffffffu, alpha, 0);
    for (int j = lane; j < D; j += 32)
        atomicAdd(&out[d0 * D + j], alpha * xl[s * D + j]);
}

// ------------------------- BatchNorm + ELU -------------------------
__global__ void k_bnzero() {
    int c = threadIdx.x;
    g_bnsum[c] = 0.f; g_bnsq[c] = 0.f;
}

__global__ void k_bnstats(const float* __restrict__ A) {
    int c = threadIdx.x % DL;
    int part = threadIdx.x / DL;
    int rbase = blockIdx.x * 256 + part * 128;
    float s = 0.f, q = 0.f;
    for (int r = 0; r < 128; r++) {
        float v = A[(rbase + r) * DL + c];
        s += v; q += v * v;
    }
    atomicAdd(&g_bnsum[c], s);
    atomicAdd(&g_bnsq[c], q);
}

__global__ void k_bnapply(const float* __restrict__ A, float* __restrict__ out,
                          const float* __restrict__ gamma, const float* __restrict__ beta) {
    int idx = blockIdx.x * blockDim.x + threadIdx.x;
    if (idx >= NN * DL) return;
    int c = idx & (DL - 1);
    float mu = g_bnsum[c] * (1.f / NN);
    float var = g_bnsq[c] * (1.f / NN) - mu * mu;
    float y = (A[idx] - mu) * rsqrtf(var + 1e-5f) * gamma[c] + beta[c];
    out[idx] = y > 0.f ? y : expm1f(y);
}

// L2-normalize rows and emit bf16 (NCE inputs only feed the scalar loss)
__global__ void k_l2c(const float* __restrict__ A, __nv_bfloat16* __restrict__ B) {
    int gt = blockIdx.x * blockDim.x + threadIdx.x;
    int row = gt >> 5, lane = gt & 31;
    if (row >= NN) return;
    const float4* p = (const float4*)(A + row * DL);
    float4 v = p[lane];
    float s = v.x * v.x + v.y * v.y + v.z * v.z + v.w * v.w;
#pragma unroll
    for (int o = 16; o; o >>= 1) s += __shfl_xor_sync(0xffffffffu, s, o);
    float inv = 1.f / sqrtf(s);
    __nv_bfloat162* q = (__nv_bfloat162*)(B + row * DL);
    q[lane * 2]     = __floats2bfloat162_rn(v.x * inv, v.y * inv);
    q[lane * 2 + 1] = __floats2bfloat162_rn(v.z * inv, v.w * inv);
}

// ------------------------- reconstruction loss -------------------------
__global__ void k_rec(const float* __restrict__ x, const float* __restrict__ h) {
    float s = 0.f;
    for (int i = blockIdx.x * blockDim.x + threadIdx.x; i < NN * DI; i += gridDim.x * blockDim.x) {
        float d = x[i] - h[i];
        s += d * d;
    }
#pragma unroll
    for (int o = 16; o; o >>= 1) s += __shfl_down_sync(0xffffffffu, s, o);
    __shared__ float red[8];
    int lane = threadIdx.x & 31, wid = threadIdx.x >> 5;
    if (lane == 0) red[wid] = s;
    __syncthreads();
    if (threadIdx.x == 0) {
        float t = 0.f;
        for (int i = 0; i < 8; i++) t += red[i];
        atomicAdd(&g_acc[0], t);
    }
}

// ------------------------- InfoNCE on tensor cores (bf16 wmma) -------------------------
// logits bounded in [-2,2] after /temp -> no online max needed.
// Block: 256 thr (8 warps), tile M=64 x N=128 per step, K=128.
// warp layout: wm = (warp&3)*16, wn = (warp>>2)*64; warp tile 16x64 (4 n-frags).
#define NCE_SMEM (64*128*2 + 128*128*2 + 8*16*68*4)
__global__ void k_nce_mma() {
    extern __shared__ char smraw[];
    __nv_bfloat16* qs = (__nv_bfloat16*)smraw;            // [64][128]
    __nv_bfloat16* ns = qs + 64 * 128;                    // [128][128] (row n, k contiguous)
    float* stb = (float*)(ns + 128 * 128);                // 8 warps x [16][68]
    __shared__ float pos2[64];
    __shared__ float rowS[64];
    __shared__ float blksum;
    int tid = threadIdx.x;
    int warp = tid >> 5, lane = tid & 31;
    int r0 = blockIdx.x * 64;

    // load q tile (64x128 bf16 = 16KB)
    {
        const uint4* src = (const uint4*)(g_q16 + r0 * DL);
        uint4* dst4 = (uint4*)qs;
#pragma unroll
        for (int i = tid; i < 64 * 128 / 8; i += 256) dst4[i] = src[i];
    }
    if (tid < 64) rowS[tid] = 0.f;
    if (tid == 0) blksum = 0.f;
    __syncthreads();

    // positives: 4 threads per row
    {
        int row = tid >> 2, part = tid & 3;
        float s = 0.f;
        const __nv_bfloat16* pr = g_p16 + (r0 + row) * DL;
        for (int k = part * 32; k < part * 32 + 32; k++)
            s += __bfloat162float(qs[row * 128 + k]) * __bfloat162float(pr[k]);
        s += __shfl_down_sync(0xffffffffu, s, 1);
        s += __shfl_down_sync(0xffffffffu, s, 2);
        if (part == 0) pos2[row] = 2.f * s;
    }

    int wm = (warp & 3) * 16;
    int wn = (warp >> 2) * 64;
    float* myst = stb + warp * (16 * 68);
    int lrow = lane >> 1;
    int lcol0 = (lane & 1) * 32;
    float sacc = 0.f;

    wmma::fragment<wmma::accumulator, 16, 16, 16, float> c[4];
    for (int n0 = 0; n0 < NN; n0 += 128) {
        __syncthreads();
        {
            const uint4* src = (const uint4*)(g_n16 + n0 * DL);
            uint4* dst4 = (uint4*)ns;
#pragma unroll
            for (int i = tid; i < 128 * 128 / 8; i += 256) dst4[i] = src[i];
        }
        __syncthreads();
#pragma unroll
        for (int j = 0; j < 4; j++) wmma::fill_fragment(c[j], 0.f);
#pragma unroll
        for (int k0 = 0; k0 < 8; k0++) {
            wmma::fragment<wmma::matrix_a, 16, 16, 16, __nv_bfloat16, wmma::row_major> a;
            wmma::load_matrix_sync(a, qs + wm * 128 + k0 * 16, 128);
#pragma unroll
            for (int j = 0; j < 4; j++) {
                wmma::fragment<wmma::matrix_b, 16, 16, 16, __nv_bfloat16, wmma::col_major> b;
                wmma::load_matrix_sync(b, ns + (wn + j * 16) * 128 + k0 * 16, 128);
                wmma::mma_sync(c[j], a, b, c[j]);
            }
        }
#pragma unroll
        for (int j = 0; j < 4; j++)
            wmma::store_matrix_sync(myst + j * 16, c[j], 68, wmma::mem_row_major);
        __syncwarp();
#pragma unroll
        for (int cc = 0; cc < 32; cc++) {
            float v = myst[lrow * 68 + lcol0 + cc];
            sacc += __expf(2.f * v);
        }
        __syncwarp();
    }
    sacc += __shfl_xor_sync(0xffffffffu, sacc, 1);
    if ((lane & 1) == 0) atomicAdd(&rowS[wm + lrow], sacc);
    __syncthreads();
    if (tid < 64) {
        float S = rowS[tid];
        float p = pos2[tid];
        float l = logf(S + __expf(p)) - p;
        atomicAdd(&blksum, l);
    }
    __syncthreads();
    if (tid == 0) atomicAdd(&g_acc[1], blksum);
}

__global__ void k_final(float* __restrict__ loss) {
    loss[0] = g_acc[0] * (1.f / (float)(NN * DI)) + 0.2f * (g_acc[1] * (1.f / (float)NN));
}

// ------------------------- host orchestration -------------------------
static void* sym_addr_helper(const void* symbol) {
    void* p = nullptr;
    cudaGetSymbolAddress(&p, symbol);
    return p;
}
#define SYM(x) ((float*)sym_addr_helper((const void*)&x))
#define SYMI(x) ((int*)sym_addr_helper((const void*)&x))
#define SYMB(x) ((__nv_bfloat16*)sym_addr_helper((const void*)&x))

static void run_gat(const int* src, const int* dst, const float* w,
                    const float* xl, const float* xr, const float* att,
                    const float* bias, float* out, int D) {
    k_prep_out<<<(NN * D) / 256, 256>>>(out, bias, D);
    k_prep_node<<<NN / 256, 256>>>();
    k_logit<<<EE / 8, 256>>>(src, dst, xl, xr, att, D);
    k_mfix<<<NN / 256, 256>>>();
    k_exp<<<EE / 256, 256>>>(dst);
    k_scatter<<<EE / 8, 256>>>(src, dst, xl, w, out, D);
}

static void run_bn(const float* A, float* out, const float* gamma, const float* beta) {
    k_bnzero<<<1, 128>>>();
    k_bnstats<<<32, 256>>>(A);
    k_bnapply<<<(NN * DL) / 256, 256>>>(A, out, gamma, beta);
}

extern "C" void kernel_launch(void* const* d_in, const int* in_sizes, int n_in,
                              void* d_out, int out_size) {
    (void)in_sizes; (void)n_in; (void)out_size;
    const float* x       = (const float*)d_in[0];
    const int*   gsi     = (const int*)d_in[1];
    const int*   gfi     = (const int*)d_in[2];
    const float* w_h     = (const float*)d_in[3];
    const float* w_h_a   = (const float*)d_in[4];
    const float* enc_Wl  = (const float*)d_in[5];
    const float* enc_Wr  = (const float*)d_in[6];
    const float* enc_att = (const float*)d_in[7];
    const float* enc_b   = (const float*)d_in[8];
    const float* dec_Wl  = (const float*)d_in[9];
    const float* dec_Wr  = (const float*)d_in[10];
    const float* dec_att = (const float*)d_in[11];
    const float* dec_b   = (const float*)d_in[12];
    const float* bn_g    = (const float*)d_in[13];
    const float* bn_b    = (const float*)d_in[14];

    float* out  = (float*)d_out;
    float* hi   = out;
    float* h    = out + H_OFF;
    float* loss = out + LOSS_OFF;

    const int* s_src = gsi;
    const int* s_dst = gsi + EE;
    const int* f_src = gfi;
    const int* f_dst = gfi + EE;

    float* xl_e = SYM(g_xl_e); float* xr_e = SYM(g_xr_e);
    float* xl_p = SYM(g_xl_p); float* xr_p = SYM(g_xr_p);
    float* xl_n = SYM(g_xl_n); float* xr_n = SYM(g_xr_n);
    float* xl_d = SYM(g_xl_d); float* xr_d = SYM(g_xr_d);
    float* gg1 = SYM(g_g1);  float* gg2 = SYM(g_g2);
    float* h0 = SYM(g_h0);   float* h1p = SYM(g_h1);  float* h2p = SYM(g_h2);
    float* Wlm = SYM(g_Wlm); float* Wrm = SYM(g_Wrm);
    int* ptmp = SYMI(g_ptmp); int* perm = SYMI(g_perm);
    __nv_bfloat16* q16 = SYMB(g_q16);
    __nv_bfloat16* p16 = SYMB(g_p16);
    __nv_bfloat16* n16 = SYMB(g_n16);
    (void)perm; (void)q16; (void)p16; (void)n16;

    cudaFuncSetAttribute(k_nce_mma, cudaFuncAttributeMaxDynamicSharedMemorySize, NCE_SMEM);

    // ---- RNG: permutation (2 stable sort rounds) + feature keep mask ----
    k_init<<<1, 32>>>();
    k_bits<<<16, 256>>>(0);
    k_rank<<<32, 256>>>(nullptr, ptmp, 1);
    k_bits<<<16, 256>>>(1);
    k_rank<<<32, 256>>>(ptmp, SYMI(g_perm), 0);
    k_keep<<<1, 128>>>();
    k_maskw<<<(DI * DL) / 256, 256>>>(enc_Wl, enc_Wr);

    // ---- encoder GEMMs ----
    dim3 ge(DL / 64, NN / 64);
    k_gemm<<<ge, 256>>>(x, enc_Wl, xl_e, DI, DL);
    k_gemm<<<ge, 256>>>(x, enc_Wr, xr_e, DI, DL);
    k_gemm<<<ge, 256>>>(x, Wlm, xl_p, DI, DL);
    k_gemm<<<ge, 256>>>(x, Wrm, xr_p, DI, DL);
    k_gatherperm<<<(NN * DL) / 256, 256>>>();

    // ---- GAT calls: hi, g1 (x_p on g_f), g2 (x_n on g_s) ----
    run_gat(s_src, s_dst, w_h, xl_e, xr_e, enc_att, enc_b, hi, DL);
    run_gat(f_src, f_dst, w_h_a, xl_p, xr_p, enc_att, enc_b, gg1, DL);
    run_gat(s_src, s_dst, w_h, xl_n, xr_n, enc_att, enc_b, gg2, DL);

    // ---- decoder ----
    dim3 gd(DI / 64, NN / 64);
    k_gemm<<<gd, 256>>>(hi, dec_Wl, xl_d, DL, DI);
    k_gemm<<<gd, 256>>>(hi, dec_Wr, xr_d, DL, DI);
    run_gat(s_src, s_dst, w_h, xl_d, xr_d, dec_att, dec_b, h, DI);

    // ---- BN + ELU + L2 norm -> bf16 ----
    run_bn(hi, h0, bn_g, bn_b);
    run_bn(gg1, h1p, bn_g, bn_b);
    run_bn(gg2, h2p, bn_g, bn_b);
    k_l2c<<<NN / 8, 256>>>(h0, SYMB(g_q16));
    k_l2c<<<NN / 8, 256>>>(h1p, SYMB(g_p16));
    k_l2c<<<NN / 8, 256>>>(h2p, SYMB(g_n16));

    // ---- losses ----
    k_rec<<<256, 256>>>(x, h);
    k_nce_mma<<<NN / 64, 256, NCE_SMEM>>>();
    k_final<<<1, 1>>>(loss);
}

// round 3
// speedup vs baseline: 1.4284x; 1.1368x over previous
#include <cuda_runtime.h>
#include <cuda_bf16.h>
#include <mma.h>
#include <stdint.h>
#include <math.h>

using namespace nvcuda;

#define NN 8192
#define EE 262144
#define DI 256
#define DL 128

#define H_OFF (NN*DL)
#define LOSS_OFF (NN*DL + NN*DI)

// ------------------------- scratch (__device__ globals) -------------------------
__device__ float g_xl_e[NN*DL];
__device__ float g_xr_e[NN*DL];
__device__ float g_xl_p[NN*DL];
__device__ float g_xr_p[NN*DL];
__device__ float g_xl_n[NN*DL];
__device__ float g_xr_n[NN*DL];
__device__ float g_xl_d[NN*DI];
__device__ float g_xr_d[NN*DI];
__device__ float g_g1[NN*DL];
__device__ float g_g2[NN*DL];
__device__ float g_h0[NN*DL];
__device__ float g_h1[NN*DL];
__device__ float g_h2[NN*DL];
__device__ __nv_bfloat16 g_q16[NN*DL];
__device__ __nv_bfloat16 g_p16[NN*DL];
__device__ __nv_bfloat16 g_n16[NN*DL];
__device__ float g_logit[EE];
__device__ float g_Wlm[DI*DL];
__device__ float g_Wrm[DI*DL];
__device__ int g_perm[NN];
__device__ int g_ptmp[NN];
__device__ unsigned g_bits[NN];
__device__ float g_keep[DI];
__device__ unsigned g_keys[6];     // [0:2]=sub1 [2:4]=sub2 [4:6]=k2
__device__ float g_bnsum[DL];
__device__ float g_bnsq[DL];
__device__ float g_acc[2];         // [0]=rec_sum [1]=ctr_sum

// CSR scratch (per graph)
__device__ int g_deg[NN];
__device__ int g_cur[NN];
__device__ int g_rp_s[NN+1];
__device__ int g_src_s[EE];
__device__ int g_dst_s[EE];
__device__ float g_w_s[EE];
__device__ int g_rp_f[NN+1];
__device__ int g_src_f[EE];
__device__ int g_dst_f[EE];
__device__ float g_w_f[EE];

// ------------------------- threefry2x32-20 -------------------------
__device__ __forceinline__ void tfry(uint32_t k0, uint32_t k1, uint32_t x0, uint32_t x1,
                                     uint32_t* o0, uint32_t* o1) {
    uint32_t ks2 = k0 ^ k1 ^ 0x1BD11BDAu;
    x0 += k0; x1 += k1;
#define RR(r) { x0 += x1; x1 = (x1 << (r)) | (x1 >> (32 - (r))); x1 ^= x0; }
    RR(13) RR(15) RR(26) RR(6)  x0 += k1;  x1 += ks2 + 1u;
    RR(17) RR(29) RR(16) RR(24) x0 += ks2; x1 += k0 + 2u;
    RR(13) RR(15) RR(26) RR(6)  x0 += k0;  x1 += k1 + 3u;
    RR(17) RR(29) RR(16) RR(24) x0 += k1;  x1 += ks2 + 4u;
    RR(13) RR(15) RR(26) RR(6)  x0 += ks2; x1 += k0 + 5u;
#undef RR
    *o0 = x0; *o1 = x1;
}

__global__ void k_init() {
    if (threadIdx.x == 0) {
        uint32_t a0, a1, b0, b1;
        tfry(0u, 42u, 0u, 2u, &a0, &a1);
        tfry(0u, 42u, 1u, 3u, &b0, &b1);
        uint32_t k1_0 = a0, k1_1 = b0;
        uint32_t k2_0 = a1, k2_1 = b1;
        uint32_t c0, c1, d0, d1;
        tfry(k1_0, k1_1, 0u, 2u, &c0, &c1);
        tfry(k1_0, k1_1, 1u, 3u, &d0, &d1);
        uint32_t kA0 = c0, kA1 = d0;
        g_keys[0] = c1; g_keys[1] = d1;
        uint32_t e0, e1, f0, f1;
        tfry(kA0, kA1, 0u, 2u, &e0, &e1);
        tfry(kA0, kA1, 1u, 3u, &f0, &f1);
        g_keys[2] = e1; g_keys[3] = f1;
        g_keys[4] = k2_0; g_keys[5] = k2_1;
        g_acc[0] = 0.f; g_acc[1] = 0.f;
    }
}

__global__ void k_bits(int which) {
    int i = blockIdx.x * blockDim.x + threadIdx.x;
    if (i >= NN / 2) return;
    uint32_t lo, hi;
    tfry(g_keys[which * 2], g_keys[which * 2 + 1], (uint32_t)i, (uint32_t)(i + NN / 2), &lo, &hi);
    g_bits[i] = lo; g_bits[i + NN / 2] = hi;
}

__global__ void k_rank(const int* __restrict__ pin, int* __restrict__ pout, int use_identity) {
    int i = blockIdx.x * blockDim.x + threadIdx.x;
    if (i >= NN) return;
    unsigned long long ki = (((unsigned long long)g_bits[i]) << 13) | (unsigned)i;
    int rank = 0;
    for (int j = 0; j < NN; j++) {
        unsigned long long kj = (((unsigned long long)g_bits[j]) << 13) | (unsigned)j;
        rank += (kj < ki);
    }
    pout[rank] = use_identity ? i : pin[i];
}

__global__ void k_keep() {
    int i = threadIdx.x;
    if (i >= DI / 2) return;
    uint32_t lo, hi;
    tfry(g_keys[4], g_keys[5], (uint32_t)i, (uint32_t)(i + DI / 2), &lo, &hi);
    float ulo = __uint_as_float((lo >> 9) | 0x3f800000u) - 1.0f;
    float uhi = __uint_as_float((hi >> 9) | 0x3f800000u) - 1.0f;
    g_keep[i] = (ulo >= 0.3f) ? 1.f : 0.f;
    g_keep[i + DI / 2] = (uhi >= 0.3f) ? 1.f : 0.f;
}

__global__ void k_maskw(const float* __restrict__ Wl, const float* __restrict__ Wr) {
    int idx = blockIdx.x * blockDim.x + threadIdx.x;
    if (idx >= DI * DL) return;
    float kmask = g_keep[idx / DL];
    g_Wlm[idx] = kmask * Wl[idx];
    g_Wrm[idx] = kmask * Wr[idx];
}

// ------------------------- CSR build (counting sort by dst) -------------------------
__global__ void k_zero_deg() {
    int i = blockIdx.x * blockDim.x + threadIdx.x;
    if (i < NN) g_deg[i] = 0;
}

__global__ void k_hist(const int* __restrict__ dst) {
    int e = blockIdx.x * blockDim.x + threadIdx.x;
    if (e < EE) atomicAdd(&g_deg[dst[e]], 1);
}

// exclusive scan over NN=8192 ints, one block of 1024 threads, 8 per thread
__global__ void k_scan(int* __restrict__ rp) {
    __shared__ int wsum[32];
    int tid = threadIdx.x;
    int lane = tid & 31, w = tid >> 5;
    int loc[8]; int s = 0;
#pragma unroll
    for (int i = 0; i < 8; i++) { loc[i] = g_deg[tid * 8 + i]; s += loc[i]; }
    int ss = s;
#pragma unroll
    for (int o = 1; o < 32; o <<= 1) { int v = __shfl_up_sync(0xffffffffu, ss, o); if (lane >= o) ss += v; }
    if (lane == 31) wsum[w] = ss;
    __syncthreads();
    if (w == 0) {
        int v = wsum[lane];
#pragma unroll
        for (int o = 1; o < 32; o <<= 1) { int u = __shfl_up_sync(0xffffffffu, v, o); if (lane >= o) v += u; }
        wsum[lane] = v;
    }
    __syncthreads();
    int base = ss - s + (w > 0 ? wsum[w - 1] : 0);
#pragma unroll
    for (int i = 0; i < 8; i++) { rp[tid * 8 + i] = base; base += loc[i]; }
    if (tid == 1023) rp[NN] = base;
}

__global__ void k_cpcur(const int* __restrict__ rp) {
    int i = blockIdx.x * blockDim.x + threadIdx.x;
    if (i < NN) g_cur[i] = rp[i];
}

__global__ void k_fill(const int* __restrict__ src, const int* __restrict__ dst,
                       const float* __restrict__ w,
                       int* __restrict__ srcS, int* __restrict__ dstS, float* __restrict__ wS) {
    int e = blockIdx.x * blockDim.x + threadIdx.x;
    if (e >= EE) return;
    int d = dst[e];
    int pos = atomicAdd(&g_cur[d], 1);
    srcS[pos] = src[e];
    dstS[pos] = d;
    wS[pos] = w[e];
}

// ------------------------- GEMM: C[M,D] = A[M,K] @ B[K,D], 64x64 tiles -------------------------
__global__ void k_gemm(const float* __restrict__ A, const float* __restrict__ B,
                       float* __restrict__ C, int K, int D) {
    __shared__ float As[16 * 68];
    __shared__ float Bs[16 * 68];
    int tid = threadIdx.x;
    int tx = tid & 15, ty = tid >> 4;
    int row0 = blockIdx.y * 64, col0 = blockIdx.x * 64;
    float acc[4][4] = {};
    for (int k0 = 0; k0 < K; k0 += 16) {
#pragma unroll
        for (int t = 0; t < 4; t++) {
            int idx = tid + t * 256;
            int ka = idx & 15, r = idx >> 4;
            As[ka * 68 + r] = A[(row0 + r) * K + k0 + ka];
            int c = idx & 63, kb = idx >> 6;
            Bs[kb * 68 + c] = B[(k0 + kb) * D + col0 + c];
        }
        __syncthreads();
#pragma unroll
        for (int kk = 0; kk < 16; kk++) {
            float4 a = *(const float4*)&As[kk * 68 + ty * 4];
            float4 b = *(const float4*)&Bs[kk * 68 + tx * 4];
            acc[0][0] += a.x * b.x; acc[0][1] += a.x * b.y; acc[0][2] += a.x * b.z; acc[0][3] += a.x * b.w;
            acc[1][0] += a.y * b.x; acc[1][1] += a.y * b.y; acc[1][2] += a.y * b.z; acc[1][3] += a.y * b.w;
            acc[2][0] += a.z * b.x; acc[2][1] += a.z * b.y; acc[2][2] += a.z * b.z; acc[2][3] += a.z * b.w;
            acc[3][0] += a.w * b.x; acc[3][1] += a.w * b.y; acc[3][2] += a.w * b.z; acc[3][3] += a.w * b.w;
        }
        __syncthreads();
    }
#pragma unroll
    for (int i = 0; i < 4; i++) {
        float4 o = make_float4(acc[i][0], acc[i][1], acc[i][2], acc[i][3]);
        *(float4*)&C[(row0 + ty * 4 + i) * D + col0 + tx * 4] = o;
    }
}

__global__ void k_gatherperm() {
    int idx = blockIdx.x * blockDim.x + threadIdx.x;
    if (idx >= NN * DL) return;
    int i = idx / DL, d = idx % DL;
    int p = g_perm[i];
    g_xl_n[idx] = g_xl_e[p * DL + d];
    g_xr_n[idx] = g_xr_e[p * DL + d];
}

// ------------------------- GAT via CSR (no atomics) -------------------------
// logits for sorted edges: warp per edge
template<int D>
__global__ void k_logitS(const int* __restrict__ srcS, const int* __restrict__ dstS,
                         const float* __restrict__ xl, const float* __restrict__ xr,
                         const float* __restrict__ att) {
    int gt = blockIdx.x * blockDim.x + threadIdx.x;
    int k = gt >> 5, lane = gt & 31;
    if (k >= EE) return;
    int s = srcS[k], d = dstS[k];
    const float4* xls = (const float4*)(xl + s * D);
    const float4* xrd = (const float4*)(xr + d * D);
    const float4* a4 = (const float4*)att;
    float acc = 0.f;
#pragma unroll
    for (int t = 0; t < D / 128; t++) {
        float4 a = xls[lane + t * 32];
        float4 b = xrd[lane + t * 32];
        float4 w = a4[lane + t * 32];
        float vx = a.x + b.x; vx = vx > 0.f ? vx : 0.2f * vx;
        float vy = a.y + b.y; vy = vy > 0.f ? vy : 0.2f * vy;
        float vz = a.z + b.z; vz = vz > 0.f ? vz : 0.2f * vz;
        float vw = a.w + b.w; vw = vw > 0.f ? vw : 0.2f * vw;
        acc += vx * w.x + vy * w.y + vz * w.z + vw * w.w;
    }
#pragma unroll
    for (int o = 16; o; o >>= 1) acc += __shfl_down_sync(0xffffffffu, acc, o);
    if (lane == 0) g_logit[k] = acc;
}

// warp per node: softmax over in-edges + weighted gather-accumulate
template<int D>
__global__ void k_node(const int* __restrict__ rp, const int* __restrict__ srcS,
                       const float* __restrict__ wS, const float* __restrict__ xl,
                       const float* __restrict__ bias, float* __restrict__ out) {
    int node = (blockIdx.x * blockDim.x + threadIdx.x) >> 5;
    int lane = threadIdx.x & 31;
    if (node >= NN) return;
    int beg = rp[node], end = rp[node + 1];
    float m = -INFINITY;
    for (int k = beg + lane; k < end; k += 32) m = fmaxf(m, g_logit[k]);
#pragma unroll
    for (int o = 16; o; o >>= 1) m = fmaxf(m, __shfl_xor_sync(0xffffffffu, m, o));
    if (!isfinite(m)) m = 0.f;
    float den = 0.f;
    for (int k = beg + lane; k < end; k += 32) den += expf(g_logit[k] - m);
#pragma unroll
    for (int o = 16; o; o >>= 1) den += __shfl_xor_sync(0xffffffffu, den, o);
    float inv = 1.f / (den + 1e-16f);
    float4 acc[D / 128];
#pragma unroll
    for (int t = 0; t < D / 128; t++) acc[t] = make_float4(0.f, 0.f, 0.f, 0.f);
    for (int k = beg; k < end; k++) {
        float a = expf(g_logit[k] - m) * inv * wS[k];
        const float4* xp = (const float4*)(xl + srcS[k] * D);
#pragma unroll
        for (int t = 0; t < D / 128; t++) {
            float4 v = xp[lane + t * 32];
            acc[t].x += a * v.x; acc[t].y += a * v.y;
            acc[t].z += a * v.z; acc[t].w += a * v.w;
        }
    }
    float4* op = (float4*)(out + node * D);
    const float4* bp = (const float4*)bias;
#pragma unroll
    for (int t = 0; t < D / 128; t++) {
        float4 b = bp[lane + t * 32];
        float4 o = make_float4(acc[t].x + b.x, acc[t].y + b.y, acc[t].z + b.z, acc[t].w + b.w);
        op[lane + t * 32] = o;
    }
}

// ------------------------- BatchNorm + ELU -------------------------
__global__ void k_bnzero() {
    int c = threadIdx.x;
    g_bnsum[c] = 0.f; g_bnsq[c] = 0.f;
}

__global__ void k_bnstats(const float* __restrict__ A) {
    int c = threadIdx.x % DL;
    int part = threadIdx.x / DL;
    int rbase = blockIdx.x * 256 + part * 128;
    float s = 0.f, q = 0.f;
    for (int r = 0; r < 128; r++) {
        float v = A[(rbase + r) * DL + c];
        s += v; q += v * v;
    }
    atomicAdd(&g_bnsum[c], s);
    atomicAdd(&g_bnsq[c], q);
}

__global__ void k_bnapply(const float* __restrict__ A, float* __restrict__ out,
                          const float* __restrict__ gamma, const float* __restrict__ beta) {
    int idx = blockIdx.x * blockDim.x + threadIdx.x;
    if (idx >= NN * DL) return;
    int c = idx & (DL - 1);
    float mu = g_bnsum[c] * (1.f / NN);
    float var = g_bnsq[c] * (1.f / NN) - mu * mu;
    float y = (A[idx] - mu) * rsqrtf(var + 1e-5f) * gamma[c] + beta[c];
    out[idx] = y > 0.f ? y : expm1f(y);
}

// L2-normalize rows and emit bf16 (NCE inputs only feed the scalar loss)
__global__ void k_l2c(const float* __restrict__ A, __nv_bfloat16* __restrict__ B) {
    int gt = blockIdx.x * blockDim.x + threadIdx.x;
    int row = gt >> 5, lane = gt & 31;
    if (row >= NN) return;
    const float4* p = (const float4*)(A + row * DL);
    float4 v = p[lane];
    float s = v.x * v.x + v.y * v.y + v.z * v.z + v.w * v.w;
#pragma unroll
    for (int o = 16; o; o >>= 1) s += __shfl_xor_sync(0xffffffffu, s, o);
    float inv = 1.f / sqrtf(s);
    __nv_bfloat162* q = (__nv_bfloat162*)(B + row * DL);
    q[lane * 2]     = __floats2bfloat162_rn(v.x * inv, v.y * inv);
    q[lane * 2 + 1] = __floats2bfloat162_rn(v.z * inv, v.w * inv);
}

// ------------------------- reconstruction loss -------------------------
__global__ void k_rec(const float* __restrict__ x, const float* __restrict__ h) {
    float s = 0.f;
    for (int i = blockIdx.x * blockDim.x + threadIdx.x; i < NN * DI; i += gridDim.x * blockDim.x) {
        float d = x[i] - h[i];
        s += d * d;
    }
#pragma unroll
    for (int o = 16; o; o >>= 1) s += __shfl_down_sync(0xffffffffu, s, o);
    __shared__ float red[8];
    int lane = threadIdx.x & 31, wid = threadIdx.x >> 5;
    if (lane == 0) red[wid] = s;
    __syncthreads();
    if (threadIdx.x == 0) {
        float t = 0.f;
        for (int i = 0; i < 8; i++) t += red[i];
        atomicAdd(&g_acc[0], t);
    }
}

// ------------------------- InfoNCE on tensor cores (bf16 wmma) -------------------------
#define NCE_SMEM (64*128*2 + 128*128*2 + 8*16*68*4)
__global__ void k_nce_mma() {
    extern __shared__ char smraw[];
    __nv_bfloat16* qs = (__nv_bfloat16*)smraw;            // [64][128]
    __nv_bfloat16* ns = qs + 64 * 128;                    // [128][128]
    float* stb = (float*)(ns + 128 * 128);                // 8 warps x [16][68]
    __shared__ float pos2[64];
    __shared__ float rowS[64];
    __shared__ float blksum;
    int tid = threadIdx.x;
    int warp = tid >> 5, lane = tid & 31;
    int r0 = blockIdx.x * 64;

    {
        const uint4* src = (const uint4*)(g_q16 + r0 * DL);
        uint4* dst4 = (uint4*)qs;
#pragma unroll
        for (int i = tid; i < 64 * 128 / 8; i += 256) dst4[i] = src[i];
    }
    if (tid < 64) rowS[tid] = 0.f;
    if (tid == 0) blksum = 0.f;
    __syncthreads();

    {
        int row = tid >> 2, part = tid & 3;
        float s = 0.f;
        const __nv_bfloat16* pr = g_p16 + (r0 + row) * DL;
        for (int k = part * 32; k < part * 32 + 32; k++)
            s += __bfloat162float(qs[row * 128 + k]) * __bfloat162float(pr[k]);
        s += __shfl_down_sync(0xffffffffu, s, 1);
        s += __shfl_down_sync(0xffffffffu, s, 2);
        if (part == 0) pos2[row] = 2.f * s;
    }

    int wm = (warp & 3) * 16;
    int wn = (warp >> 2) * 64;
    float* myst = stb + warp * (16 * 68);
    int lrow = lane >> 1;
    int lcol0 = (lane & 1) * 32;
    float sacc = 0.f;

    wmma::fragment<wmma::accumulator, 16, 16, 16, float> c[4];
    for (int n0 = 0; n0 < NN; n0 += 128) {
        __syncthreads();
        {
            const uint4* src = (const uint4*)(g_n16 + n0 * DL);
            uint4* dst4 = (uint4*)ns;
#pragma unroll
            for (int i = tid; i < 128 * 128 / 8; i += 256) dst4[i] = src[i];
        }
        __syncthreads();
#pragma unroll
        for (int j = 0; j < 4; j++) wmma::fill_fragment(c[j], 0.f);
#pragma unroll
        for (int k0 = 0; k0 < 8; k0++) {
            wmma::fragment<wmma::matrix_a, 16, 16, 16, __nv_bfloat16, wmma::row_major> a;
            wmma::load_matrix_sync(a, qs + wm * 128 + k0 * 16, 128);
#pragma unroll
            for (int j = 0; j < 4; j++) {
                wmma::fragment<wmma::matrix_b, 16, 16, 16, __nv_bfloat16, wmma::col_major> b;
                wmma::load_matrix_sync(b, ns + (wn + j * 16) * 128 + k0 * 16, 128);
                wmma::mma_sync(c[j], a, b, c[j]);
            }
        }
#pragma unroll
        for (int j = 0; j < 4; j++)
            wmma::store_matrix_sync(myst + j * 16, c[j], 68, wmma::mem_row_major);
        __syncwarp();
#pragma unroll
        for (int cc = 0; cc < 32; cc++) {
            float v = myst[lrow * 68 + lcol0 + cc];
            sacc += __expf(2.f * v);
        }
        __syncwarp();
    }
    sacc += __shfl_xor_sync(0xffffffffu, sacc, 1);
    if ((lane & 1) == 0) atomicAdd(&rowS[wm + lrow], sacc);
    __syncthreads();
    if (tid < 64) {
        float S = rowS[tid];
        float p = pos2[tid];
        float l = logf(S + __expf(p)) - p;
        atomicAdd(&blksum, l);
    }
    __syncthreads();
    if (tid == 0) atomicAdd(&g_acc[1], blksum);
}

__global__ void k_final(float* __restrict__ loss) {
    loss[0] = g_acc[0] * (1.f / (float)(NN * DI)) + 0.2f * (g_acc[1] * (1.f / (float)NN));
}

// ------------------------- host orchestration -------------------------
static void* sym_addr_helper(const void* symbol) {
    void* p = nullptr;
    cudaGetSymbolAddress(&p, symbol);
    return p;
}
#define SYM(x) ((float*)sym_addr_helper((const void*)&x))
#define SYMI(x) ((int*)sym_addr_helper((const void*)&x))
#define SYMB(x) ((__nv_bfloat16*)sym_addr_helper((const void*)&x))

static void build_csr(const int* src, const int* dst, const float* w,
                      int* rp, int* srcS, int* dstS, float* wS) {
    k_zero_deg<<<NN / 256, 256>>>();
    k_hist<<<EE / 256, 256>>>(dst);
    k_scan<<<1, 1024>>>(rp);
    k_cpcur<<<NN / 256, 256>>>(rp);
    k_fill<<<EE / 256, 256>>>(src, dst, w, srcS, dstS, wS);
}

template<int D>
static void run_gat(const int* rp, const int* srcS, const int* dstS, const float* wS,
                    const float* xl, const float* xr, const float* att,
                    const float* bias, float* out) {
    k_logitS<D><<<EE / 8, 256>>>(srcS, dstS, xl, xr, att);
    k_node<D><<<NN / 8, 256>>>(rp, srcS, wS, xl, bias, out);
}

static void run_bn(const float* A, float* out, const float* gamma, const float* beta) {
    k_bnzero<<<1, 128>>>();
    k_bnstats<<<32, 256>>>(A);
    k_bnapply<<<(NN * DL) / 256, 256>>>(A, out, gamma, beta);
}

extern "C" void kernel_launch(void* const* d_in, const int* in_sizes, int n_in,
                              void* d_out, int out_size) {
    (void)in_sizes; (void)n_in; (void)out_size;
    const float* x       = (const float*)d_in[0];
    const int*   gsi     = (const int*)d_in[1];
    const int*   gfi     = (const int*)d_in[2];
    const float* w_h     = (const float*)d_in[3];
    const float* w_h_a   = (const float*)d_in[4];
    const float* enc_Wl  = (const float*)d_in[5];
    const float* enc_Wr  = (const float*)d_in[6];
    const float* enc_att = (const float*)d_in[7];
    const float* enc_b   = (const float*)d_in[8];
    const float* dec_Wl  = (const float*)d_in[9];
    const float* dec_Wr  = (const float*)d_in[10];
    const float* dec_att = (const float*)d_in[11];
    const float* dec_b   = (const float*)d_in[12];
    const float* bn_g    = (const float*)d_in[13];
    const float* bn_b    = (const float*)d_in[14];

    float* out  = (float*)d_out;
    float* hi   = out;
    float* h    = out + H_OFF;
    float* loss = out + LOSS_OFF;

    const int* s_src = gsi;
    const int* s_dst = gsi + EE;
    const int* f_src = gfi;
    const int* f_dst = gfi + EE;

    float* xl_e = SYM(g_xl_e); float* xr_e = SYM(g_xr_e);
    float* xl_p = SYM(g_xl_p); float* xr_p = SYM(g_xr_p);
    float* xl_n = SYM(g_xl_n); float* xr_n = SYM(g_xr_n);
    float* xl_d = SYM(g_xl_d); float* xr_d = SYM(g_xr_d);
    float* gg1 = SYM(g_g1);  float* gg2 = SYM(g_g2);
    float* h0 = SYM(g_h0);   float* h1p = SYM(g_h1);  float* h2p = SYM(g_h2);
    float* Wlm = SYM(g_Wlm); float* Wrm = SYM(g_Wrm);
    int* ptmp = SYMI(g_ptmp);

    int* rp_s = SYMI(g_rp_s); int* src_s = SYMI(g_src_s);
    int* dst_s = SYMI(g_dst_s); float* w_s = SYM(g_w_s);
    int* rp_f = SYMI(g_rp_f); int* src_f = SYMI(g_src_f);
    int* dst_f = SYMI(g_dst_f); float* w_f = SYM(g_w_f);

    cudaFuncSetAttribute(k_nce_mma, cudaFuncAttributeMaxDynamicSharedMemorySize, NCE_SMEM);

    // ---- RNG: permutation + feature keep mask ----
    k_init<<<1, 32>>>();
    k_bits<<<16, 256>>>(0);
    k_rank<<<32, 256>>>(nullptr, ptmp, 1);
    k_bits<<<16, 256>>>(1);
    k_rank<<<32, 256>>>(ptmp, SYMI(g_perm), 0);
    k_keep<<<1, 128>>>();
    k_maskw<<<(DI * DL) / 256, 256>>>(enc_Wl, enc_Wr);

    // ---- CSR builds ----
    build_csr(s_src, s_dst, w_h, rp_s, src_s, dst_s, w_s);
    build_csr(f_src, f_dst, w_h_a, rp_f, src_f, dst_f, w_f);

    // ---- encoder GEMMs ----
    dim3 ge(DL / 64, NN / 64);
    k_gemm<<<ge, 256>>>(x, enc_Wl, xl_e, DI, DL);
    k_gemm<<<ge, 256>>>(x, enc_Wr, xr_e, DI, DL);
    k_gemm<<<ge, 256>>>(x, Wlm, xl_p, DI, DL);
    k_gemm<<<ge, 256>>>(x, Wrm, xr_p, DI, DL);
    k_gatherperm<<<(NN * DL) / 256, 256>>>();

    // ---- GAT calls: hi, g1 (x_p on g_f), g2 (x_n on g_s) ----
    run_gat<DL>(rp_s, src_s, dst_s, w_s, xl_e, xr_e, enc_att, enc_b, hi);
    run_gat<DL>(rp_f, src_f, dst_f, w_f, xl_p, xr_p, enc_att, enc_b, gg1);
    run_gat<DL>(rp_s, src_s, dst_s, w_s, xl_n, xr_n, enc_att, enc_b, gg2);

    // ---- decoder ----
    dim3 gd(DI / 64, NN / 64);
    k_gemm<<<gd, 256>>>(hi, dec_Wl, xl_d, DL, DI);
    k_gemm<<<gd, 256>>>(hi, dec_Wr, xr_d, DL, DI);
    run_gat<DI>(rp_s, src_s, dst_s, w_s, xl_d, xr_d, dec_att, dec_b, h);

    // ---- BN + ELU + L2 norm -> bf16 ----
    run_bn(hi, h0, bn_g, bn_b);
    run_bn(gg1, h1p, bn_g, bn_b);
    run_bn(gg2, h2p, bn_g, bn_b);
    k_l2c<<<NN / 8, 256>>>(h0, SYMB(g_q16));
    k_l2c<<<NN / 8, 256>>>(h1p, SYMB(g_p16));
    k_l2c<<<NN / 8, 256>>>(h2p, SYMB(g_n16));

    // ---- losses ----
    k_rec<<<256, 256>>>(x, h);
    k_nce_mma<<<NN / 64, 256, NCE_SMEM>>>();
    k_final<<<1, 1>>>(loss);
}

// round 4
// speedup vs baseline: 2.0791x; 1.4555x over previous
#include <cuda_runtime.h>
#include <cuda_bf16.h>
#include <mma.h>
#include <stdint.h>
#include <math.h>

using namespace nvcuda;

#define NN 8192
#define EE 262144
#define DI 256
#define DL 128

#define H_OFF (NN*DL)
#define LOSS_OFF (NN*DL + NN*DI)

// ------------------------- scratch (__device__ globals) -------------------------
__device__ float g_xl_e[NN*DL];
__device__ float g_xr_e[NN*DL];
__device__ float g_xl_p[NN*DL];
__device__ float g_xr_p[NN*DL];
__device__ float g_xl_n[NN*DL];
__device__ float g_xr_n[NN*DL];
__device__ float g_xl_d[NN*DI];
__device__ float g_xr_d[NN*DI];
__device__ float g_g1[NN*DL];
__device__ float g_g2[NN*DL];
__device__ __nv_bfloat16 g_q16[NN*DL];
__device__ __nv_bfloat16 g_p16[NN*DL];
__device__ __nv_bfloat16 g_n16[NN*DL];
__device__ float g_logit[EE];
__device__ int g_perm[NN];
__device__ int g_ptmp[NN];
__device__ unsigned g_bits[NN];
__device__ float g_keep[DI];
__device__ unsigned g_keys[6];     // [0:2]=sub1 [2:4]=sub2 [4:6]=k2
__device__ float g_bns[3][DL];
__device__ float g_bnq[3][DL];
__device__ float g_acc[2];         // [0]=rec_sum [1]=ctr_sum

// bf16 split buffers
__device__ __nv_bfloat16 g_Ah[NN*DI];
__device__ __nv_bfloat16 g_Al[NN*DI];
__device__ __nv_bfloat16 g_Bh[DI*512];
__device__ __nv_bfloat16 g_Bl[DI*512];

// CSR scratch (per graph)
__device__ int g_deg_s[NN];
__device__ int g_deg_f[NN];
__device__ int g_cur_s[NN];
__device__ int g_cur_f[NN];
__device__ int g_rp_s[NN+1];
__device__ int g_src_s[EE];
__device__ int g_dst_s[EE];
__device__ float g_w_s[EE];
__device__ int g_rp_f[NN+1];
__device__ int g_src_f[EE];
__device__ int g_dst_f[EE];
__device__ float g_w_f[EE];

// ------------------------- threefry2x32-20 -------------------------
__device__ __forceinline__ void tfry(uint32_t k0, uint32_t k1, uint32_t x0, uint32_t x1,
                                     uint32_t* o0, uint32_t* o1) {
    uint32_t ks2 = k0 ^ k1 ^ 0x1BD11BDAu;
    x0 += k0; x1 += k1;
#define RR(r) { x0 += x1; x1 = (x1 << (r)) | (x1 >> (32 - (r))); x1 ^= x0; }
    RR(13) RR(15) RR(26) RR(6)  x0 += k1;  x1 += ks2 + 1u;
    RR(17) RR(29) RR(16) RR(24) x0 += ks2; x1 += k0 + 2u;
    RR(13) RR(15) RR(26) RR(6)  x0 += k0;  x1 += k1 + 3u;
    RR(17) RR(29) RR(16) RR(24) x0 += k1;  x1 += ks2 + 4u;
    RR(13) RR(15) RR(26) RR(6)  x0 += ks2; x1 += k0 + 5u;
#undef RR
    *o0 = x0; *o1 = x1;
}

// grid-wide init: keys (t==0) + zero deg/bn arrays
__global__ void k_init() {
    int t = blockIdx.x * blockDim.x + threadIdx.x;
    if (t == 0) {
        uint32_t a0, a1, b0, b1;
        tfry(0u, 42u, 0u, 2u, &a0, &a1);
        tfry(0u, 42u, 1u, 3u, &b0, &b1);
        uint32_t k1_0 = a0, k1_1 = b0;
        uint32_t k2_0 = a1, k2_1 = b1;
        uint32_t c0, c1, d0, d1;
        tfry(k1_0, k1_1, 0u, 2u, &c0, &c1);
        tfry(k1_0, k1_1, 1u, 3u, &d0, &d1);
        uint32_t kA0 = c0, kA1 = d0;
        g_keys[0] = c1; g_keys[1] = d1;
        uint32_t e0, e1, f0, f1;
        tfry(kA0, kA1, 0u, 2u, &e0, &e1);
        tfry(kA0, kA1, 1u, 3u, &f0, &f1);
        g_keys[2] = e1; g_keys[3] = f1;
        g_keys[4] = k2_0; g_keys[5] = k2_1;
        g_acc[0] = 0.f; g_acc[1] = 0.f;
    }
    if (t < NN) { g_deg_s[t] = 0; g_deg_f[t] = 0; }
    if (t < DL) {
        g_bns[0][t] = 0.f; g_bns[1][t] = 0.f; g_bns[2][t] = 0.f;
        g_bnq[0][t] = 0.f; g_bnq[1][t] = 0.f; g_bnq[2][t] = 0.f;
    }
}

__global__ void k_bits(int which) {
    int i = blockIdx.x * blockDim.x + threadIdx.x;
    if (i >= NN / 2) return;
    uint32_t lo, hi;
    tfry(g_keys[which * 2], g_keys[which * 2 + 1], (uint32_t)i, (uint32_t)(i + NN / 2), &lo, &hi);
    g_bits[i] = lo; g_bits[i + NN / 2] = hi;
}

// warp per element, lane-strided rank count
__global__ void k_rank2(const int* __restrict__ pin, int* __restrict__ pout, int use_identity) {
    int gt = blockIdx.x * blockDim.x + threadIdx.x;
    int i = gt >> 5, lane = gt & 31;
    if (i >= NN) return;
    unsigned long long ki = (((unsigned long long)g_bits[i]) << 13) | (unsigned)i;
    int rank = 0;
    for (int j = lane; j < NN; j += 32) {
        unsigned long long kj = (((unsigned long long)g_bits[j]) << 13) | (unsigned)j;
        rank += (kj < ki);
    }
#pragma unroll
    for (int o = 16; o; o >>= 1) rank += __shfl_down_sync(0xffffffffu, rank, o);
    if (lane == 0) pout[rank] = use_identity ? i : pin[i];
}

__global__ void k_keep() {
    int i = threadIdx.x;
    if (i >= DI / 2) return;
    uint32_t lo, hi;
    tfry(g_keys[4], g_keys[5], (uint32_t)i, (uint32_t)(i + DI / 2), &lo, &hi);
    float ulo = __uint_as_float((lo >> 9) | 0x3f800000u) - 1.0f;
    float uhi = __uint_as_float((hi >> 9) | 0x3f800000u) - 1.0f;
    g_keep[i] = (ulo >= 0.3f) ? 1.f : 0.f;
    g_keep[i + DI / 2] = (uhi >= 0.3f) ? 1.f : 0.f;
}

// ------------------------- CSR build (counting sort by dst) -------------------------
__global__ void k_hist(const int* __restrict__ dst, int* __restrict__ deg) {
    int e = blockIdx.x * blockDim.x + threadIdx.x;
    if (e < EE) atomicAdd(&deg[dst[e]], 1);
}

// exclusive scan over NN=8192 ints, one block of 1024 threads, 8 per thread
__global__ void k_scan(int* __restrict__ rp, const int* __restrict__ deg, int* __restrict__ cur) {
    __shared__ int wsum[32];
    int tid = threadIdx.x;
    int lane = tid & 31, w = tid >> 5;
    int loc[8]; int s = 0;
#pragma unroll
    for (int i = 0; i < 8; i++) { loc[i] = deg[tid * 8 + i]; s += loc[i]; }
    int ss = s;
#pragma unroll
    for (int o = 1; o < 32; o <<= 1) { int v = __shfl_up_sync(0xffffffffu, ss, o); if (lane >= o) ss += v; }
    if (lane == 31) wsum[w] = ss;
    __syncthreads();
    if (w == 0) {
        int v = wsum[lane];
#pragma unroll
        for (int o = 1; o < 32; o <<= 1) { int u = __shfl_up_sync(0xffffffffu, v, o); if (lane >= o) v += u; }
        wsum[lane] = v;
    }
    __syncthreads();
    int base = ss - s + (w > 0 ? wsum[w - 1] : 0);
#pragma unroll
    for (int i = 0; i < 8; i++) { rp[tid * 8 + i] = base; cur[tid * 8 + i] = base; base += loc[i]; }
    if (tid == 1023) rp[NN] = base;
}

__global__ void k_fill(const int* __restrict__ src, const int* __restrict__ dst,
                       const float* __restrict__ w, int* __restrict__ cur,
                       int* __restrict__ srcS, int* __restrict__ dstS, float* __restrict__ wS) {
    int e = blockIdx.x * blockDim.x + threadIdx.x;
    if (e >= EE) return;
    int d = dst[e];
    int pos = atomicAdd(&cur[d], 1);
    srcS[pos] = src[e];
    dstS[pos] = d;
    wS[pos] = w[e];
}

// ------------------------- bf16x3 split GEMM on tensor cores -------------------------
__global__ void k_cvt(const float* __restrict__ A, __nv_bfloat16* __restrict__ hi,
                      __nv_bfloat16* __restrict__ lo, int n) {
    int i = blockIdx.x * blockDim.x + threadIdx.x;
    if (i >= n) return;
    float a = A[i];
    __nv_bfloat16 h = __float2bfloat16_rn(a);
    hi[i] = h;
    lo[i] = __float2bfloat16_rn(a - __bfloat162float(h));
}

// enc B pack: [256][512] = [Wl | Wr | keep*Wl | keep*Wr]
__global__ void k_packB_enc(const float* __restrict__ Wl, const float* __restrict__ Wr) {
    int idx = blockIdx.x * blockDim.x + threadIdx.x;
    if (idx >= DI * 512) return;
    int k = idx >> 9, c = idx & 511;
    float v;
    if (c < 128) v = Wl[k * 128 + c];
    else if (c < 256) v = Wr[k * 128 + c - 128];
    else if (c < 384) v = g_keep[k] * Wl[k * 128 + c - 256];
    else v = g_keep[k] * Wr[k * 128 + c - 384];
    __nv_bfloat16 h = __float2bfloat16_rn(v);
    g_Bh[idx] = h;
    g_Bl[idx] = __float2bfloat16_rn(v - __bfloat162float(h));
}

// dec B pack: [128][512] = [dec_Wl | dec_Wr]
__global__ void k_packB_dec(const float* __restrict__ Wl, const float* __restrict__ Wr) {
    int idx = blockIdx.x * blockDim.x + threadIdx.x;
    if (idx >= DL * 512) return;
    int k = idx >> 9, c = idx & 511;
    float v = (c < 256) ? Wl[k * 256 + c] : Wr[k * 256 + c - 256];
    __nv_bfloat16 h = __float2bfloat16_rn(v);
    g_Bh[idx] = h;
    g_Bl[idx] = __float2bfloat16_rn(v - __bfloat162float(h));
}

// C[M,512] = A[M,K] @ B[K,512] via bf16x3; epilogue splits columns into out buffers.
__global__ void k_gemm3(const __nv_bfloat16* __restrict__ Ah, const __nv_bfloat16* __restrict__ Al,
                        int K, float* o0, float* o1, float* o2, float* o3, int lgw) {
    __shared__ __nv_bfloat16 sAh[64 * 40], sAl[64 * 40];
    __shared__ __nv_bfloat16 sBh[32 * 136], sBl[32 * 136];
    int tid = threadIdx.x;
    int warp = tid >> 5;
    int wm = warp >> 2, wn = warp & 3;
    int row0 = blockIdx.y * 64, col0 = blockIdx.x * 128;
    wmma::fragment<wmma::accumulator, 16, 16, 16, float> c[2][2];
#pragma unroll
    for (int i = 0; i < 2; i++)
#pragma unroll
        for (int j = 0; j < 2; j++) wmma::fill_fragment(c[i][j], 0.f);
    int r = tid >> 2, q = tid & 3;
    for (int kp = 0; kp < K; kp += 32) {
        __syncthreads();
        *(uint4*)&sAh[r * 40 + q * 8] = *(const uint4*)&Ah[(row0 + r) * K + kp + q * 8];
        *(uint4*)&sAl[r * 40 + q * 8] = *(const uint4*)&Al[(row0 + r) * K + kp + q * 8];
#pragma unroll
        for (int v = 0; v < 2; v++) {
            int idx = tid + v * 256;
            int k = idx >> 4, nq = idx & 15;
            *(uint4*)&sBh[k * 136 + nq * 8] = *(const uint4*)&g_Bh[(kp + k) * 512 + col0 + nq * 8];
            *(uint4*)&sBl[k * 136 + nq * 8] = *(const uint4*)&g_Bl[(kp + k) * 512 + col0 + nq * 8];
        }
        __syncthreads();
#pragma unroll
        for (int ks = 0; ks < 32; ks += 16) {
            wmma::fragment<wmma::matrix_a, 16, 16, 16, __nv_bfloat16, wmma::row_major> ah[2], al[2];
            wmma::fragment<wmma::matrix_b, 16, 16, 16, __nv_bfloat16, wmma::row_major> bh[2], bl[2];
#pragma unroll
            for (int i = 0; i < 2; i++) {
                wmma::load_matrix_sync(ah[i], &sAh[(wm * 32 + i * 16) * 40 + ks], 40);
                wmma::load_matrix_sync(al[i], &sAl[(wm * 32 + i * 16) * 40 + ks], 40);
            }
#pragma unroll
            for (int j = 0; j < 2; j++) {
                wmma::load_matrix_sync(bh[j], &sBh[ks * 136 + wn * 32 + j * 16], 136);
                wmma::load_matrix_sync(bl[j], &sBl[ks * 136 + wn * 32 + j * 16], 136);
            }
#pragma unroll
            for (int i = 0; i < 2; i++)
#pragma unroll
                for (int j = 0; j < 2; j++) {
                    wmma::mma_sync(c[i][j], ah[i], bh[j], c[i][j]);
                    wmma::mma_sync(c[i][j], ah[i], bl[j], c[i][j]);
                    wmma::mma_sync(c[i][j], al[i], bh[j], c[i][j]);
                }
        }
    }
    float* ob[4] = {o0, o1, o2, o3};
    int W = 1 << lgw, msk = W - 1;
#pragma unroll
    for (int i = 0; i < 2; i++)
#pragma unroll
        for (int j = 0; j < 2; j++) {
            int colg = col0 + wn * 32 + j * 16;
            float* dst = ob[colg >> lgw] + (size_t)(row0 + wm * 32 + i * 16) * W + (colg & msk);
            wmma::store_matrix_sync(dst, c[i][j], W, wmma::mem_row_major);
        }
}

__global__ void k_gatherperm() {
    int idx = blockIdx.x * blockDim.x + threadIdx.x;
    if (idx >= NN * DL) return;
    int i = idx / DL, d = idx % DL;
    int p = g_perm[i];
    g_xl_n[idx] = g_xl_e[p * DL + d];
    g_xr_n[idx] = g_xr_e[p * DL + d];
}

// ------------------------- GAT via CSR (no atomics) -------------------------
template<int D>
__global__ void k_logitS(const int* __restrict__ srcS, const int* __restrict__ dstS,
                         const float* __restrict__ xl, const float* __restrict__ xr,
                         const float* __restrict__ att) {
    int gt = blockIdx.x * blockDim.x + threadIdx.x;
    int k = gt >> 5, lane = gt & 31;
    if (k >= EE) return;
    int s = srcS[k], d = dstS[k];
    const float4* xls = (const float4*)(xl + s * D);
    const float4* xrd = (const float4*)(xr + d * D);
    const float4* a4 = (const float4*)att;
    float acc = 0.f;
#pragma unroll
    for (int t = 0; t < D / 128; t++) {
        float4 a = xls[lane + t * 32];
        float4 b = xrd[lane + t * 32];
        float4 w = a4[lane + t * 32];
        float vx = a.x + b.x; vx = vx > 0.f ? vx : 0.2f * vx;
        float vy = a.y + b.y; vy = vy > 0.f ? vy : 0.2f * vy;
        float vz = a.z + b.z; vz = vz > 0.f ? vz : 0.2f * vz;
        float vw = a.w + b.w; vw = vw > 0.f ? vw : 0.2f * vw;
        acc += vx * w.x + vy * w.y + vz * w.z + vw * w.w;
    }
#pragma unroll
    for (int o = 16; o; o >>= 1) acc += __shfl_down_sync(0xffffffffu, acc, o);
    if (lane == 0) g_logit[k] = acc;
}

template<int D>
__global__ void k_node(const int* __restrict__ rp, const int* __restrict__ srcS,
                       const float* __restrict__ wS, const float* __restrict__ xl,
                       const float* __restrict__ bias, float* __restrict__ out) {
    int node = (blockIdx.x * blockDim.x + threadIdx.x) >> 5;
    int lane = threadIdx.x & 31;
    if (node >= NN) return;
    int beg = rp[node], end = rp[node + 1];
    float m = -INFINITY;
    for (int k = beg + lane; k < end; k += 32) m = fmaxf(m, g_logit[k]);
#pragma unroll
    for (int o = 16; o; o >>= 1) m = fmaxf(m, __shfl_xor_sync(0xffffffffu, m, o));
    if (!isfinite(m)) m = 0.f;
    float den = 0.f;
    for (int k = beg + lane; k < end; k += 32) den += expf(g_logit[k] - m);
#pragma unroll
    for (int o = 16; o; o >>= 1) den += __shfl_xor_sync(0xffffffffu, den, o);
    float inv = 1.f / (den + 1e-16f);
    float4 acc[D / 128];
#pragma unroll
    for (int t = 0; t < D / 128; t++) acc[t] = make_float4(0.f, 0.f, 0.f, 0.f);
    for (int k = beg; k < end; k++) {
        float a = expf(g_logit[k] - m) * inv * wS[k];
        const float4* xp = (const float4*)(xl + srcS[k] * D);
#pragma unroll
        for (int t = 0; t < D / 128; t++) {
            float4 v = xp[lane + t * 32];
            acc[t].x += a * v.x; acc[t].y += a * v.y;
            acc[t].z += a * v.z; acc[t].w += a * v.w;
        }
    }
    float4* op = (float4*)(out + node * D);
    const float4* bp = (const float4*)bias;
#pragma unroll
    for (int t = 0; t < D / 128; t++) {
        float4 b = bp[lane + t * 32];
        float4 o = make_float4(acc[t].x + b.x, acc[t].y + b.y, acc[t].z + b.z, acc[t].w + b.w);
        op[lane + t * 32] = o;
    }
}

// ------------------------- BatchNorm stats (3 inputs, gridDim.y) -------------------------
__global__ void k_bnstats3(const float* __restrict__ a0, const float* __restrict__ a1,
                           const float* __restrict__ a2) {
    int y = blockIdx.y;
    const float* A = (y == 0) ? a0 : (y == 1 ? a1 : a2);
    int c = threadIdx.x % DL;
    int part = threadIdx.x / DL;
    int rbase = blockIdx.x * 256 + part * 128;
    float s = 0.f, q = 0.f;
    for (int r = 0; r < 128; r++) {
        float v = A[(rbase + r) * DL + c];
        s += v; q += v * v;
    }
    atomicAdd(&g_bns[y][c], s);
    atomicAdd(&g_bnq[y][c], q);
}

// fused BN apply + ELU + L2 norm + bf16 convert; warp per row, gridDim.y picks input
__global__ void k_bnl2(const float* __restrict__ a0, const float* __restrict__ a1,
                       const float* __restrict__ a2,
                       const float* __restrict__ gamma, const float* __restrict__ beta) {
    int y = blockIdx.y;
    const float* A = (y == 0) ? a0 : (y == 1 ? a1 : a2);
    __nv_bfloat16* B = (y == 0) ? g_q16 : (y == 1 ? g_p16 : g_n16);
    int gt = blockIdx.x * blockDim.x + threadIdx.x;
    int row = gt >> 5, lane = gt & 31;
    if (row >= NN) return;
    float4 v = ((const float4*)(A + row * DL))[lane];
    float4 sm = ((const float4*)g_bns[y])[lane];
    float4 sq = ((const float4*)g_bnq[y])[lane];
    float4 ga = ((const float4*)gamma)[lane];
    float4 be = ((const float4*)beta)[lane];
    float mu, var, t;
#define BNE(comp) \
    mu = sm.comp * (1.f / NN); var = sq.comp * (1.f / NN) - mu * mu; \
    t = (v.comp - mu) * rsqrtf(var + 1e-5f) * ga.comp + be.comp; \
    v.comp = t > 0.f ? t : expm1f(t);
    BNE(x) BNE(y) BNE(z) BNE(w)
#undef BNE
    float s = v.x * v.x + v.y * v.y + v.z * v.z + v.w * v.w;
#pragma unroll
    for (int o = 16; o; o >>= 1) s += __shfl_xor_sync(0xffffffffu, s, o);
    float inv = 1.f / sqrtf(s);
    __nv_bfloat162* qp = (__nv_bfloat162*)(B + row * DL);
    qp[lane * 2]     = __floats2bfloat162_rn(v.x * inv, v.y * inv);
    qp[lane * 2 + 1] = __floats2bfloat162_rn(v.z * inv, v.w * inv);
}

// ------------------------- reconstruction loss -------------------------
__global__ void k_rec(const float* __restrict__ x, const float* __restrict__ h) {
    float s = 0.f;
    for (int i = blockIdx.x * blockDim.x + threadIdx.x; i < NN * DI; i += gridDim.x * blockDim.x) {
        float d = x[i] - h[i];
        s += d * d;
    }
#pragma unroll
    for (int o = 16; o; o >>= 1) s += __shfl_down_sync(0xffffffffu, s, o);
    __shared__ float red[8];
    int lane = threadIdx.x & 31, wid = threadIdx.x >> 5;
    if (lane == 0) red[wid] = s;
    __syncthreads();
    if (threadIdx.x == 0) {
        float t = 0.f;
        for (int i = 0; i < 8; i++) t += red[i];
        atomicAdd(&g_acc[0], t);
    }
}

// ------------------------- InfoNCE on tensor cores (bf16 wmma) -------------------------
#define NCE_SMEM (64*128*2 + 128*128*2 + 8*16*68*4)
__global__ void k_nce_mma() {
    extern __shared__ char smraw[];
    __nv_bfloat16* qs = (__nv_bfloat16*)smraw;            // [64][128]
    __nv_bfloat16* ns = qs + 64 * 128;                    // [128][128]
    float* stb = (float*)(ns + 128 * 128);                // 8 warps x [16][68]
    __shared__ float pos2[64];
    __shared__ float rowS[64];
    __shared__ float blksum;
    int tid = threadIdx.x;
    int warp = tid >> 5, lane = tid & 31;
    int r0 = blockIdx.x * 64;

    {
        const uint4* src = (const uint4*)(g_q16 + r0 * DL);
        uint4* dst4 = (uint4*)qs;
#pragma unroll
        for (int i = tid; i < 64 * 128 / 8; i += 256) dst4[i] = src[i];
    }
    if (tid < 64) rowS[tid] = 0.f;
    if (tid == 0) blksum = 0.f;
    __syncthreads();

    {
        int row = tid >> 2, part = tid & 3;
        float s = 0.f;
        const __nv_bfloat16* pr = g_p16 + (r0 + row) * DL;
        for (int k = part * 32; k < part * 32 + 32; k++)
            s += __bfloat162float(qs[row * 128 + k]) * __bfloat162float(pr[k]);
        s += __shfl_down_sync(0xffffffffu, s, 1);
        s += __shfl_down_sync(0xffffffffu, s, 2);
        if (part == 0) pos2[row] = 2.f * s;
    }

    int wm = (warp & 3) * 16;
    int wn = (warp >> 2) * 64;
    float* myst = stb + warp * (16 * 68);
    int lrow = lane >> 1;
    int lcol0 = (lane & 1) * 32;
    float sacc = 0.f;

    wmma::fragment<wmma::accumulator, 16, 16, 16, float> c[4];
    for (int n0 = 0; n0 < NN; n0 += 128) {
        __syncthreads();
        {
            const uint4* src = (const uint4*)(g_n16 + n0 * DL);
            uint4* dst4 = (uint4*)ns;
#pragma unroll
            for (int i = tid; i < 128 * 128 / 8; i += 256) dst4[i] = src[i];
        }
        __syncthreads();
#pragma unroll
        for (int j = 0; j < 4; j++) wmma::fill_fragment(c[j], 0.f);
#pragma unroll
        for (int k0 = 0; k0 < 8; k0++) {
            wmma::fragment<wmma::matrix_a, 16, 16, 16, __nv_bfloat16, wmma::row_major> a;
            wmma::load_matrix_sync(a, qs + wm * 128 + k0 * 16, 128);
#pragma unroll
            for (int j = 0; j < 4; j++) {
                wmma::fragment<wmma::matrix_b, 16, 16, 16, __nv_bfloat16, wmma::col_major> b;
                wmma::load_matrix_sync(b, ns + (wn + j * 16) * 128 + k0 * 16, 128);
                wmma::mma_sync(c[j], a, b, c[j]);
            }
        }
#pragma unroll
        for (int j = 0; j < 4; j++)
            wmma::store_matrix_sync(myst + j * 16, c[j], 68, wmma::mem_row_major);
        __syncwarp();
#pragma unroll
        for (int cc = 0; cc < 32; cc++) {
            float v = myst[lrow * 68 + lcol0 + cc];
            sacc += __expf(2.f * v);
        }
        __syncwarp();
    }
    sacc += __shfl_xor_sync(0xffffffffu, sacc, 1);
    if ((lane & 1) == 0) atomicAdd(&rowS[wm + lrow], sacc);
    __syncthreads();
    if (tid < 64) {
        float S = rowS[tid];
        float p = pos2[tid];
        float l = logf(S + __expf(p)) - p;
        atomicAdd(&blksum, l);
    }
    __syncthreads();
    if (tid == 0) atomicAdd(&g_acc[1], blksum);
}

__global__ void k_final(float* __restrict__ loss) {
    loss[0] = g_acc[0] * (1.f / (float)(NN * DI)) + 0.2f * (g_acc[1] * (1.f / (float)NN));
}

// ------------------------- host orchestration -------------------------
static void* sym_addr_helper(const void* symbol) {
    void* p = nullptr;
    cudaGetSymbolAddress(&p, symbol);
    return p;
}
#define SYM(x) ((float*)sym_addr_helper((const void*)&x))
#define SYMI(x) ((int*)sym_addr_helper((const void*)&x))
#define SYMB(x) ((__nv_bfloat16*)sym_addr_helper((const void*)&x))

template<int D>
static void run_gat(const int* rp, const int* srcS, const int* dstS, const float* wS,
                    const float* xl, const float* xr, const float* att,
                    const float* bias, float* out) {
    k_logitS<D><<<EE / 8, 256>>>(srcS, dstS, xl, xr, att);
    k_node<D><<<NN / 8, 256>>>(rp, srcS, wS, xl, bias, out);
}

extern "C" void kernel_launch(void* const* d_in, const int* in_sizes, int n_in,
                              void* d_out, int out_size) {
    (void)in_sizes; (void)n_in; (void)out_size;
    const float* x       = (const float*)d_in[0];
    const int*   gsi     = (const int*)d_in[1];
    const int*   gfi     = (const int*)d_in[2];
    const float* w_h     = (const float*)d_in[3];
    const float* w_h_a   = (const float*)d_in[4];
    const float* enc_Wl  = (const float*)d_in[5];
    const float* enc_Wr  = (const float*)d_in[6];
    const float* enc_att = (const float*)d_in[7];
    const float* enc_b   = (const float*)d_in[8];
    const float* dec_Wl  = (const float*)d_in[9];
    const float* dec_Wr  = (const float*)d_in[10];
    const float* dec_att = (const float*)d_in[11];
    const float* dec_b   = (const float*)d_in[12];
    const float* bn_g    = (const float*)d_in[13];
    const float* bn_b    = (const float*)d_in[14];

    float* out  = (float*)d_out;
    float* hi   = out;
    float* h    = out + H_OFF;
    float* loss = out + LOSS_OFF;

    const int* s_src = gsi;
    const int* s_dst = gsi + EE;
    const int* f_src = gfi;
    const int* f_dst = gfi + EE;

    float* xl_e = SYM(g_xl_e); float* xr_e = SYM(g_xr_e);
    float* xl_p = SYM(g_xl_p); float* xr_p = SYM(g_xr_p);
    float* xl_n = SYM(g_xl_n); float* xr_n = SYM(g_xr_n);
    float* xl_d = SYM(g_xl_d); float* xr_d = SYM(g_xr_d);
    float* gg1 = SYM(g_g1);  float* gg2 = SYM(g_g2);
    int* ptmp = SYMI(g_ptmp);

    int* rp_s = SYMI(g_rp_s); int* src_s = SYMI(g_src_s);
    int* dst_s = SYMI(g_dst_s); float* w_s = SYM(g_w_s);
    int* rp_f = SYMI(g_rp_f); int* src_f = SYMI(g_src_f);
    int* dst_f = SYMI(g_dst_f); float* w_f = SYM(g_w_f);
    int* deg_s = SYMI(g_deg_s); int* deg_f = SYMI(g_deg_f);
    int* cur_s = SYMI(g_cur_s); int* cur_f = SYMI(g_cur_f);
    __nv_bfloat16* Ah = SYMB(g_Ah); __nv_bfloat16* Al = SYMB(g_Al);

    cudaFuncSetAttribute(k_nce_mma, cudaFuncAttributeMaxDynamicSharedMemorySize, NCE_SMEM);

    // ---- init + RNG ----
    k_init<<<32, 256>>>();
    k_bits<<<16, 256>>>(0);
    k_rank2<<<NN / 8, 256>>>(nullptr, ptmp, 1);
    k_bits<<<16, 256>>>(1);
    k_rank2<<<NN / 8, 256>>>(ptmp, SYMI(g_perm), 0);
    k_keep<<<1, 128>>>();

    // ---- CSR builds ----
    k_hist<<<EE / 256, 256>>>(s_dst, deg_s);
    k_scan<<<1, 1024>>>(rp_s, deg_s, cur_s);
    k_fill<<<EE / 256, 256>>>(s_src, s_dst, w_h, cur_s, src_s, dst_s, w_s);
    k_hist<<<EE / 256, 256>>>(f_dst, deg_f);
    k_scan<<<1, 1024>>>(rp_f, deg_f, cur_f);
    k_fill<<<EE / 256, 256>>>(f_src, f_dst, w_h_a, cur_f, src_f, dst_f, w_f);

    // ---- encoder: one fused N=512 GEMM (xl_e | xr_e | xl_p | xr_p) ----
    k_cvt<<<(NN * DI) / 256, 256>>>(x, Ah, Al, NN * DI);
    k_packB_enc<<<(DI * 512) / 256, 256>>>(enc_Wl, enc_Wr);
    {
        dim3 g(4, NN / 64);
        k_gemm3<<<g, 256>>>(Ah, Al, DI, xl_e, xr_e, xl_p, xr_p, 7);
    }
    k_gatherperm<<<(NN * DL) / 256, 256>>>();

    // ---- GAT calls: hi, g1 (x_p on g_f), g2 (x_n on g_s) ----
    run_gat<DL>(rp_s, src_s, dst_s, w_s, xl_e, xr_e, enc_att, enc_b, hi);
    run_gat<DL>(rp_f, src_f, dst_f, w_f, xl_p, xr_p, enc_att, enc_b, gg1);
    run_gat<DL>(rp_s, src_s, dst_s, w_s, xl_n, xr_n, enc_att, enc_b, gg2);

    // ---- decoder: one fused N=512 GEMM (xl_d | xr_d) ----
    k_cvt<<<(NN * DL) / 256, 256>>>(hi, Ah, Al, NN * DL);
    k_packB_dec<<<(DL * 512) / 256, 256>>>(dec_Wl, dec_Wr);
    {
        dim3 g(4, NN / 64);
        k_gemm3<<<g, 256>>>(Ah, Al, DL, xl_d, xr_d, xl_d, xr_d, 8);
    }
    run_gat<DI>(rp_s, src_s, dst_s, w_s, xl_d, xr_d, dec_att, dec_b, h);

    // ---- BN + ELU + L2 norm -> bf16 (fused) ----
    {
        dim3 g(32, 3);
        k_bnstats3<<<g, 256>>>(hi, gg1, gg2);
        dim3 g2(NN / 8, 3);
        k_bnl2<<<g2, 256>>>(hi, gg1, gg2, bn_g, bn_b);
    }

    // ---- losses ----
    k_rec<<<256, 256>>>(x, h);
    k_nce_mma<<<NN / 64, 256, NCE_SMEM>>>();
    k_final<<<1, 1>>>(loss);
}

// round 5
// speedup vs baseline: 2.2514x; 1.0829x over previous
#include <cuda_runtime.h>
#include <cuda_bf16.h>
#include <mma.h>
#include <stdint.h>
#include <math.h>

using namespace nvcuda;

#define NN 8192
#define EE 262144
#define DI 256
#define DL 128

#define H_OFF (NN*DL)
#define LOSS_OFF (NN*DL + NN*DI)

// ------------------------- scratch (__device__ globals) -------------------------
__device__ float g_xl_e[NN*DL];
__device__ float g_xr_e[NN*DL];
__device__ float g_xl_p[NN*DL];
__device__ float g_xr_p[NN*DL];
__device__ float g_xl_n[NN*DL];
__device__ float g_xr_n[NN*DL];
__device__ float g_xl_d[NN*DI];
__device__ float g_xr_d[NN*DI];
__device__ float g_g1[NN*DL];
__device__ float g_g2[NN*DL];
__device__ __nv_bfloat16 g_q16[NN*DL];
__device__ __nv_bfloat16 g_p16[NN*DL];
__device__ __nv_bfloat16 g_n16[NN*DL];
__device__ int g_perm[NN];
__device__ int g_ptmp[NN];
__device__ unsigned g_bits[NN];
__device__ float g_keep[DI];
__device__ unsigned g_keys[6];     // [0:2]=sub1 [2:4]=sub2 [4:6]=k2
__device__ float g_bns[3][DL];
__device__ float g_bnq[3][DL];
__device__ float g_acc[2];         // [0]=rec_sum [1]=ctr_sum

// bf16 split buffers
__device__ __nv_bfloat16 g_Ah[NN*DI];
__device__ __nv_bfloat16 g_Al[NN*DI];
__device__ __nv_bfloat16 g_Bh[DI*512];
__device__ __nv_bfloat16 g_Bl[DI*512];

// CSR scratch (per graph)
__device__ int g_deg_s[NN];
__device__ int g_deg_f[NN];
__device__ int g_cur_s[NN];
__device__ int g_cur_f[NN];
__device__ int g_rp_s[NN+1];
__device__ int g_src_s[EE];
__device__ float g_w_s[EE];
__device__ int g_rp_f[NN+1];
__device__ int g_src_f[EE];
__device__ float g_w_f[EE];

// ------------------------- threefry2x32-20 -------------------------
__device__ __forceinline__ void tfry(uint32_t k0, uint32_t k1, uint32_t x0, uint32_t x1,
                                     uint32_t* o0, uint32_t* o1) {
    uint32_t ks2 = k0 ^ k1 ^ 0x1BD11BDAu;
    x0 += k0; x1 += k1;
#define RR(r) { x0 += x1; x1 = (x1 << (r)) | (x1 >> (32 - (r))); x1 ^= x0; }
    RR(13) RR(15) RR(26) RR(6)  x0 += k1;  x1 += ks2 + 1u;
    RR(17) RR(29) RR(16) RR(24) x0 += ks2; x1 += k0 + 2u;
    RR(13) RR(15) RR(26) RR(6)  x0 += k0;  x1 += k1 + 3u;
    RR(17) RR(29) RR(16) RR(24) x0 += k1;  x1 += ks2 + 4u;
    RR(13) RR(15) RR(26) RR(6)  x0 += ks2; x1 += k0 + 5u;
#undef RR
    *o0 = x0; *o1 = x1;
}

// grid-wide init: keys (t==0) + zero deg/bn arrays
__global__ void k_init() {
    int t = blockIdx.x * blockDim.x + threadIdx.x;
    if (t == 0) {
        uint32_t a0, a1, b0, b1;
        tfry(0u, 42u, 0u, 2u, &a0, &a1);
        tfry(0u, 42u, 1u, 3u, &b0, &b1);
        uint32_t k1_0 = a0, k1_1 = b0;
        uint32_t k2_0 = a1, k2_1 = b1;
        uint32_t c0, c1, d0, d1;
        tfry(k1_0, k1_1, 0u, 2u, &c0, &c1);
        tfry(k1_0, k1_1, 1u, 3u, &d0, &d1);
        uint32_t kA0 = c0, kA1 = d0;
        g_keys[0] = c1; g_keys[1] = d1;
        uint32_t e0, e1, f0, f1;
        tfry(kA0, kA1, 0u, 2u, &e0, &e1);
        tfry(kA0, kA1, 1u, 3u, &f0, &f1);
        g_keys[2] = e1; g_keys[3] = f1;
        g_keys[4] = k2_0; g_keys[5] = k2_1;
        g_acc[0] = 0.f; g_acc[1] = 0.f;
    }
    if (t < NN) { g_deg_s[t] = 0; g_deg_f[t] = 0; }
    if (t < DL) {
        g_bns[0][t] = 0.f; g_bns[1][t] = 0.f; g_bns[2][t] = 0.f;
        g_bnq[0][t] = 0.f; g_bnq[1][t] = 0.f; g_bnq[2][t] = 0.f;
    }
}

__global__ void k_bits(int which) {
    int i = blockIdx.x * blockDim.x + threadIdx.x;
    if (i >= NN / 2) return;
    uint32_t lo, hi;
    tfry(g_keys[which * 2], g_keys[which * 2 + 1], (uint32_t)i, (uint32_t)(i + NN / 2), &lo, &hi);
    g_bits[i] = lo; g_bits[i + NN / 2] = hi;
}

// warp per element, lane-strided rank count
__global__ void k_rank2(const int* __restrict__ pin, int* __restrict__ pout, int use_identity) {
    int gt = blockIdx.x * blockDim.x + threadIdx.x;
    int i = gt >> 5, lane = gt & 31;
    if (i >= NN) return;
    unsigned long long ki = (((unsigned long long)g_bits[i]) << 13) | (unsigned)i;
    int rank = 0;
    for (int j = lane; j < NN; j += 32) {
        unsigned long long kj = (((unsigned long long)g_bits[j]) << 13) | (unsigned)j;
        rank += (kj < ki);
    }
#pragma unroll
    for (int o = 16; o; o >>= 1) rank += __shfl_down_sync(0xffffffffu, rank, o);
    if (lane == 0) pout[rank] = use_identity ? i : pin[i];
}

__global__ void k_keep() {
    int i = threadIdx.x;
    if (i >= DI / 2) return;
    uint32_t lo, hi;
    tfry(g_keys[4], g_keys[5], (uint32_t)i, (uint32_t)(i + DI / 2), &lo, &hi);
    float ulo = __uint_as_float((lo >> 9) | 0x3f800000u) - 1.0f;
    float uhi = __uint_as_float((hi >> 9) | 0x3f800000u) - 1.0f;
    g_keep[i] = (ulo >= 0.3f) ? 1.f : 0.f;
    g_keep[i + DI / 2] = (uhi >= 0.3f) ? 1.f : 0.f;
}

// ------------------------- CSR build (counting sort by dst) -------------------------
__global__ void k_hist(const int* __restrict__ dst, int* __restrict__ deg) {
    int e = blockIdx.x * blockDim.x + threadIdx.x;
    if (e < EE) atomicAdd(&deg[dst[e]], 1);
}

// exclusive scan over NN=8192 ints, one block of 1024 threads, 8 per thread
__global__ void k_scan(int* __restrict__ rp, const int* __restrict__ deg, int* __restrict__ cur) {
    __shared__ int wsum[32];
    int tid = threadIdx.x;
    int lane = tid & 31, w = tid >> 5;
    int loc[8]; int s = 0;
#pragma unroll
    for (int i = 0; i < 8; i++) { loc[i] = deg[tid * 8 + i]; s += loc[i]; }
    int ss = s;
#pragma unroll
    for (int o = 1; o < 32; o <<= 1) { int v = __shfl_up_sync(0xffffffffu, ss, o); if (lane >= o) ss += v; }
    if (lane == 31) wsum[w] = ss;
    __syncthreads();
    if (w == 0) {
        int v = wsum[lane];
#pragma unroll
        for (int o = 1; o < 32; o <<= 1) { int u = __shfl_up_sync(0xffffffffu, v, o); if (lane >= o) v += u; }
        wsum[lane] = v;
    }
    __syncthreads();
    int base = ss - s + (w > 0 ? wsum[w - 1] : 0);
#pragma unroll
    for (int i = 0; i < 8; i++) { rp[tid * 8 + i] = base; cur[tid * 8 + i] = base; base += loc[i]; }
    if (tid == 1023) rp[NN] = base;
}

__global__ void k_fill(const int* __restrict__ src, const int* __restrict__ dst,
                       const float* __restrict__ w, int* __restrict__ cur,
                       int* __restrict__ srcS, float* __restrict__ wS) {
    int e = blockIdx.x * blockDim.x + threadIdx.x;
    if (e >= EE) return;
    int d = dst[e];
    int pos = atomicAdd(&cur[d], 1);
    srcS[pos] = src[e];
    wS[pos] = w[e];
}

// ------------------------- bf16x3 split GEMM on tensor cores -------------------------
__global__ void k_cvt(const float* __restrict__ A, __nv_bfloat16* __restrict__ hi,
                      __nv_bfloat16* __restrict__ lo, int n) {
    int i = blockIdx.x * blockDim.x + threadIdx.x;
    if (i >= n) return;
    float a = A[i];
    __nv_bfloat16 h = __float2bfloat16_rn(a);
    hi[i] = h;
    lo[i] = __float2bfloat16_rn(a - __bfloat162float(h));
}

// enc B pack: [256][512] = [Wl | Wr | keep*Wl | keep*Wr]
__global__ void k_packB_enc(const float* __restrict__ Wl, const float* __restrict__ Wr) {
    int idx = blockIdx.x * blockDim.x + threadIdx.x;
    if (idx >= DI * 512) return;
    int k = idx >> 9, c = idx & 511;
    float v;
    if (c < 128) v = Wl[k * 128 + c];
    else if (c < 256) v = Wr[k * 128 + c - 128];
    else if (c < 384) v = g_keep[k] * Wl[k * 128 + c - 256];
    else v = g_keep[k] * Wr[k * 128 + c - 384];
    __nv_bfloat16 h = __float2bfloat16_rn(v);
    g_Bh[idx] = h;
    g_Bl[idx] = __float2bfloat16_rn(v - __bfloat162float(h));
}

// dec B pack: [128][512] = [dec_Wl | dec_Wr]
__global__ void k_packB_dec(const float* __restrict__ Wl, const float* __restrict__ Wr) {
    int idx = blockIdx.x * blockDim.x + threadIdx.x;
    if (idx >= DL * 512) return;
    int k = idx >> 9, c = idx & 511;
    float v = (c < 256) ? Wl[k * 256 + c] : Wr[k * 256 + c - 256];
    __nv_bfloat16 h = __float2bfloat16_rn(v);
    g_Bh[idx] = h;
    g_Bl[idx] = __float2bfloat16_rn(v - __bfloat162float(h));
}

// C[M,512] = A[M,K] @ B[K,512] via bf16x3; epilogue splits columns into out buffers.
__global__ void k_gemm3(const __nv_bfloat16* __restrict__ Ah, const __nv_bfloat16* __restrict__ Al,
                        int K, float* o0, float* o1, float* o2, float* o3, int lgw) {
    __shared__ __nv_bfloat16 sAh[64 * 40], sAl[64 * 40];
    __shared__ __nv_bfloat16 sBh[32 * 136], sBl[32 * 136];
    int tid = threadIdx.x;
    int warp = tid >> 5;
    int wm = warp >> 2, wn = warp & 3;
    int row0 = blockIdx.y * 64, col0 = blockIdx.x * 128;
    wmma::fragment<wmma::accumulator, 16, 16, 16, float> c[2][2];
#pragma unroll
    for (int i = 0; i < 2; i++)
#pragma unroll
        for (int j = 0; j < 2; j++) wmma::fill_fragment(c[i][j], 0.f);
    int r = tid >> 2, q = tid & 3;
    for (int kp = 0; kp < K; kp += 32) {
        __syncthreads();
        *(uint4*)&sAh[r * 40 + q * 8] = *(const uint4*)&Ah[(row0 + r) * K + kp + q * 8];
        *(uint4*)&sAl[r * 40 + q * 8] = *(const uint4*)&Al[(row0 + r) * K + kp + q * 8];
#pragma unroll
        for (int v = 0; v < 2; v++) {
            int idx = tid + v * 256;
            int k = idx >> 4, nq = idx & 15;
            *(uint4*)&sBh[k * 136 + nq * 8] = *(const uint4*)&g_Bh[(kp + k) * 512 + col0 + nq * 8];
            *(uint4*)&sBl[k * 136 + nq * 8] = *(const uint4*)&g_Bl[(kp + k) * 512 + col0 + nq * 8];
        }
        __syncthreads();
#pragma unroll
        for (int ks = 0; ks < 32; ks += 16) {
            wmma::fragment<wmma::matrix_a, 16, 16, 16, __nv_bfloat16, wmma::row_major> ah[2], al[2];
            wmma::fragment<wmma::matrix_b, 16, 16, 16, __nv_bfloat16, wmma::row_major> bh[2], bl[2];
#pragma unroll
            for (int i = 0; i < 2; i++) {
                wmma::load_matrix_sync(ah[i], &sAh[(wm * 32 + i * 16) * 40 + ks], 40);
                wmma::load_matrix_sync(al[i], &sAl[(wm * 32 + i * 16) * 40 + ks], 40);
            }
#pragma unroll
            for (int j = 0; j < 2; j++) {
                wmma::load_matrix_sync(bh[j], &sBh[ks * 136 + wn * 32 + j * 16], 136);
                wmma::load_matrix_sync(bl[j], &sBl[ks * 136 + wn * 32 + j * 16], 136);
            }
#pragma unroll
            for (int i = 0; i < 2; i++)
#pragma unroll
                for (int j = 0; j < 2; j++) {
                    wmma::mma_sync(c[i][j], ah[i], bh[j], c[i][j]);
                    wmma::mma_sync(c[i][j], ah[i], bl[j], c[i][j]);
                    wmma::mma_sync(c[i][j], al[i], bh[j], c[i][j]);
                }
        }
    }
    float* ob[4] = {o0, o1, o2, o3};
    int W = 1 << lgw, msk = W - 1;
#pragma unroll
    for (int i = 0; i < 2; i++)
#pragma unroll
        for (int j = 0; j < 2; j++) {
            int colg = col0 + wn * 32 + j * 16;
            float* dst = ob[colg >> lgw] + (size_t)(row0 + wm * 32 + i * 16) * W + (colg & msk);
            wmma::store_matrix_sync(dst, c[i][j], W, wmma::mem_row_major);
        }
}

__global__ void k_gatherperm() {
    int idx = blockIdx.x * blockDim.x + threadIdx.x;
    if (idx >= NN * DL) return;
    int i = idx / DL, d = idx % DL;
    int p = g_perm[i];
    g_xl_n[idx] = g_xl_e[p * DL + d];
    g_xr_n[idx] = g_xr_e[p * DL + d];
}

// ------------------------- fused single-pass GAT (warp per node) -------------------------
// softmax shift removed: alpha is shift-invariant; logits ~N(0,1), expf safe.
template<int D>
__global__ void k_gat(const int* __restrict__ rp, const int* __restrict__ srcS,
                      const float* __restrict__ wS,
                      const float* __restrict__ xl, const float* __restrict__ xr,
                      const float* __restrict__ att,
                      const float* __restrict__ bias, float* __restrict__ out) {
    constexpr int T = D / 128;
    int node = (blockIdx.x * blockDim.x + threadIdx.x) >> 5;
    int lane = threadIdx.x & 31;
    if (node >= NN) return;
    int beg = rp[node], end = rp[node + 1];
    const float4* xrp = (const float4*)(xr + node * D);
    const float4* ap = (const float4*)att;
    float4 xrv[T], av[T], acc[T];
#pragma unroll
    for (int t = 0; t < T; t++) {
        xrv[t] = xrp[lane + t * 32];
        av[t] = ap[lane + t * 32];
        acc[t] = make_float4(0.f, 0.f, 0.f, 0.f);
    }
    float den = 0.f;
    for (int k = beg; k < end; k++) {
        int s = srcS[k];
        const float4* xp = (const float4*)(xl + s * D);
        float4 v[T];
        float lg = 0.f;
#pragma unroll
        for (int t = 0; t < T; t++) {
            v[t] = xp[lane + t * 32];
            float ex = v[t].x + xrv[t].x; ex = ex > 0.f ? ex : 0.2f * ex;
            float ey = v[t].y + xrv[t].y; ey = ey > 0.f ? ey : 0.2f * ey;
            float ez = v[t].z + xrv[t].z; ez = ez > 0.f ? ez : 0.2f * ez;
            float ew = v[t].w + xrv[t].w; ew = ew > 0.f ? ew : 0.2f * ew;
            lg += ex * av[t].x + ey * av[t].y + ez * av[t].z + ew * av[t].w;
        }
#pragma unroll
        for (int o = 16; o; o >>= 1) lg += __shfl_xor_sync(0xffffffffu, lg, o);
        float w = expf(lg);
        den += w;
        float a = w * wS[k];
#pragma unroll
        for (int t = 0; t < T; t++) {
            acc[t].x += a * v[t].x; acc[t].y += a * v[t].y;
            acc[t].z += a * v[t].z; acc[t].w += a * v[t].w;
        }
    }
    float inv = 1.f / (den + 1e-16f);
    float4* op = (float4*)(out + node * D);
    const float4* bp = (const float4*)bias;
#pragma unroll
    for (int t = 0; t < T; t++) {
        float4 b = bp[lane + t * 32];
        op[lane + t * 32] = make_float4(acc[t].x * inv + b.x, acc[t].y * inv + b.y,
                                        acc[t].z * inv + b.z, acc[t].w * inv + b.w);
    }
}

// ------------------------- BatchNorm stats (3 inputs, gridDim.y) -------------------------
__global__ void k_bnstats3(const float* __restrict__ a0, const float* __restrict__ a1,
                           const float* __restrict__ a2) {
    int y = blockIdx.y;
    const float* A = (y == 0) ? a0 : (y == 1 ? a1 : a2);
    int c = threadIdx.x % DL;
    int part = threadIdx.x / DL;
    int rbase = blockIdx.x * 256 + part * 128;
    float s = 0.f, q = 0.f;
    for (int r = 0; r < 128; r++) {
        float v = A[(rbase + r) * DL + c];
        s += v; q += v * v;
    }
    atomicAdd(&g_bns[y][c], s);
    atomicAdd(&g_bnq[y][c], q);
}

// fused BN apply + ELU + L2 norm + bf16 convert; warp per row, gridDim.y picks input
__global__ void k_bnl2(const float* __restrict__ a0, const float* __restrict__ a1,
                       const float* __restrict__ a2,
                       const float* __restrict__ gamma, const float* __restrict__ beta) {
    int y = blockIdx.y;
    const float* A = (y == 0) ? a0 : (y == 1 ? a1 : a2);
    __nv_bfloat16* B = (y == 0) ? g_q16 : (y == 1 ? g_p16 : g_n16);
    int gt = blockIdx.x * blockDim.x + threadIdx.x;
    int row = gt >> 5, lane = gt & 31;
    if (row >= NN) return;
    float4 v = ((const float4*)(A + row * DL))[lane];
    float4 sm = ((const float4*)g_bns[y])[lane];
    float4 sq = ((const float4*)g_bnq[y])[lane];
    float4 ga = ((const float4*)gamma)[lane];
    float4 be = ((const float4*)beta)[lane];
    float mu, var, t;
#define BNE(comp) \
    mu = sm.comp * (1.f / NN); var = sq.comp * (1.f / NN) - mu * mu; \
    t = (v.comp - mu) * rsqrtf(var + 1e-5f) * ga.comp + be.comp; \
    v.comp = t > 0.f ? t : expm1f(t);
    BNE(x) BNE(y) BNE(z) BNE(w)
#undef BNE
    float s = v.x * v.x + v.y * v.y + v.z * v.z + v.w * v.w;
#pragma unroll
    for (int o = 16; o; o >>= 1) s += __shfl_xor_sync(0xffffffffu, s, o);
    float inv = 1.f / sqrtf(s);
    __nv_bfloat162* qp = (__nv_bfloat162*)(B + row * DL);
    qp[lane * 2]     = __floats2bfloat162_rn(v.x * inv, v.y * inv);
    qp[lane * 2 + 1] = __floats2bfloat162_rn(v.z * inv, v.w * inv);
}

// ------------------------- reconstruction loss -------------------------
__global__ void k_rec(const float* __restrict__ x, const float* __restrict__ h) {
    float s = 0.f;
    for (int i = blockIdx.x * blockDim.x + threadIdx.x; i < NN * DI; i += gridDim.x * blockDim.x) {
        float d = x[i] - h[i];
        s += d * d;
    }
#pragma unroll
    for (int o = 16; o; o >>= 1) s += __shfl_down_sync(0xffffffffu, s, o);
    __shared__ float red[8];
    int lane = threadIdx.x & 31, wid = threadIdx.x >> 5;
    if (lane == 0) red[wid] = s;
    __syncthreads();
    if (threadIdx.x == 0) {
        float t = 0.f;
        for (int i = 0; i < 8; i++) t += red[i];
        atomicAdd(&g_acc[0], t);
    }
}

// ------------------------- InfoNCE on tensor cores (bf16 wmma) -------------------------
#define NCE_SMEM (64*128*2 + 128*128*2 + 8*16*68*4)
__global__ void k_nce_mma() {
    extern __shared__ char smraw[];
    __nv_bfloat16* qs = (__nv_bfloat16*)smraw;            // [64][128]
    __nv_bfloat16* ns = qs + 64 * 128;                    // [128][128]
    float* stb = (float*)(ns + 128 * 128);                // 8 warps x [16][68]
    __shared__ float pos2[64];
    __shared__ float rowS[64];
    __shared__ float blksum;
    int tid = threadIdx.x;
    int warp = tid >> 5, lane = tid & 31;
    int r0 = blockIdx.x * 64;

    {
        const uint4* src = (const uint4*)(g_q16 + r0 * DL);
        uint4* dst4 = (uint4*)qs;
#pragma unroll
        for (int i = tid; i < 64 * 128 / 8; i += 256) dst4[i] = src[i];
    }
    if (tid < 64) rowS[tid] = 0.f;
    if (tid == 0) blksum = 0.f;
    __syncthreads();

    {
        int row = tid >> 2, part = tid & 3;
        float s = 0.f;
        const __nv_bfloat16* pr = g_p16 + (r0 + row) * DL;
        for (int k = part * 32; k < part * 32 + 32; k++)
            s += __bfloat162float(qs[row * 128 + k]) * __bfloat162float(pr[k]);
        s += __shfl_down_sync(0xffffffffu, s, 1);
        s += __shfl_down_sync(0xffffffffu, s, 2);
        if (part == 0) pos2[row] = 2.f * s;
    }

    int wm = (warp & 3) * 16;
    int wn = (warp >> 2) * 64;
    float* myst = stb + warp * (16 * 68);
    int lrow = lane >> 1;
    int lcol0 = (lane & 1) * 32;
    float sacc = 0.f;

    wmma::fragment<wmma::accumulator, 16, 16, 16, float> c[4];
    for (int n0 = 0; n0 < NN; n0 += 128) {
        __syncthreads();
        {
            const uint4* src = (const uint4*)(g_n16 + n0 * DL);
            uint4* dst4 = (uint4*)ns;
#pragma unroll
            for (int i = tid; i < 128 * 128 / 8; i += 256) dst4[i] = src[i];
        }
        __syncthreads();
#pragma unroll
        for (int j = 0; j < 4; j++) wmma::fill_fragment(c[j], 0.f);
#pragma unroll
        for (int k0 = 0; k0 < 8; k0++) {
            wmma::fragment<wmma::matrix_a, 16, 16, 16, __nv_bfloat16, wmma::row_major> a;
            wmma::load_matrix_sync(a, qs + wm * 128 + k0 * 16, 128);
#pragma unroll
            for (int j = 0; j < 4; j++) {
                wmma::fragment<wmma::matrix_b, 16, 16, 16, __nv_bfloat16, wmma::col_major> b;
                wmma::load_matrix_sync(b, ns + (wn + j * 16) * 128 + k0 * 16, 128);
                wmma::mma_sync(c[j], a, b, c[j]);
            }
        }
#pragma unroll
        for (int j = 0; j < 4; j++)
            wmma::store_matrix_sync(myst + j * 16, c[j], 68, wmma::mem_row_major);
        __syncwarp();
#pragma unroll
        for (int cc = 0; cc < 32; cc++) {
            float v = myst[lrow * 68 + lcol0 + cc];
            sacc += __expf(2.f * v);
        }
        __syncwarp();
    }
    sacc += __shfl_xor_sync(0xffffffffu, sacc, 1);
    if ((lane & 1) == 0) atomicAdd(&rowS[wm + lrow], sacc);
    __syncthreads();
    if (tid < 64) {
        float S = rowS[tid];
        float p = pos2[tid];
        float l = logf(S + __expf(p)) - p;
        atomicAdd(&blksum, l);
    }
    __syncthreads();
    if (tid == 0) atomicAdd(&g_acc[1], blksum);
}

__global__ void k_final(float* __restrict__ loss) {
    loss[0] = g_acc[0] * (1.f / (float)(NN * DI)) + 0.2f * (g_acc[1] * (1.f / (float)NN));
}

// ------------------------- host orchestration -------------------------
static void* sym_addr_helper(const void* symbol) {
    void* p = nullptr;
    cudaGetSymbolAddress(&p, symbol);
    return p;
}
#define SYM(x) ((float*)sym_addr_helper((const void*)&x))
#define SYMI(x) ((int*)sym_addr_helper((const void*)&x))
#define SYMB(x) ((__nv_bfloat16*)sym_addr_helper((const void*)&x))

extern "C" void kernel_launch(void* const* d_in, const int* in_sizes, int n_in,
                              void* d_out, int out_size) {
    (void)in_sizes; (void)n_in; (void)out_size;
    const float* x       = (const float*)d_in[0];
    const int*   gsi     = (const int*)d_in[1];
    const int*   gfi     = (const int*)d_in[2];
    const float* w_h     = (const float*)d_in[3];
    const float* w_h_a   = (const float*)d_in[4];
    const float* enc_Wl  = (const float*)d_in[5];
    const float* enc_Wr  = (const float*)d_in[6];
    const float* enc_att = (const float*)d_in[7];
    const float* enc_b   = (const float*)d_in[8];
    const float* dec_Wl  = (const float*)d_in[9];
    const float* dec_Wr  = (const float*)d_in[10];
    const float* dec_att = (const float*)d_in[11];
    const float* dec_b   = (const float*)d_in[12];
    const float* bn_g    = (const float*)d_in[13];
    const float* bn_b    = (const float*)d_in[14];

    float* out  = (float*)d_out;
    float* hi   = out;
    float* h    = out + H_OFF;
    float* loss = out + LOSS_OFF;

    const int* s_src = gsi;
    const int* s_dst = gsi + EE;
    const int* f_src = gfi;
    const int* f_dst = gfi + EE;

    float* xl_e = SYM(g_xl_e); float* xr_e = SYM(g_xr_e);
    float* xl_p = SYM(g_xl_p); float* xr_p = SYM(g_xr_p);
    float* xl_n = SYM(g_xl_n); float* xr_n = SYM(g_xr_n);
    float* xl_d = SYM(g_xl_d); float* xr_d = SYM(g_xr_d);
    float* gg1 = SYM(g_g1);  float* gg2 = SYM(g_g2);
    int* ptmp = SYMI(g_ptmp);

    int* rp_s = SYMI(g_rp_s); int* src_s = SYMI(g_src_s); float* w_s = SYM(g_w_s);
    int* rp_f = SYMI(g_rp_f); int* src_f = SYMI(g_src_f); float* w_f = SYM(g_w_f);
    int* deg_s = SYMI(g_deg_s); int* deg_f = SYMI(g_deg_f);
    int* cur_s = SYMI(g_cur_s); int* cur_f = SYMI(g_cur_f);
    __nv_bfloat16* Ah = SYMB(g_Ah); __nv_bfloat16* Al = SYMB(g_Al);

    cudaFuncSetAttribute(k_nce_mma, cudaFuncAttributeMaxDynamicSharedMemorySize, NCE_SMEM);

    // ---- init + RNG ----
    k_init<<<32, 256>>>();
    k_bits<<<16, 256>>>(0);
    k_rank2<<<NN / 8, 256>>>(nullptr, ptmp, 1);
    k_bits<<<16, 256>>>(1);
    k_rank2<<<NN / 8, 256>>>(ptmp, SYMI(g_perm), 0);
    k_keep<<<1, 128>>>();

    // ---- CSR builds ----
    k_hist<<<EE / 256, 256>>>(s_dst, deg_s);
    k_scan<<<1, 1024>>>(rp_s, deg_s, cur_s);
    k_fill<<<EE / 256, 256>>>(s_src, s_dst, w_h, cur_s, src_s, w_s);
    k_hist<<<EE / 256, 256>>>(f_dst, deg_f);
    k_scan<<<1, 1024>>>(rp_f, deg_f, cur_f);
    k_fill<<<EE / 256, 256>>>(f_src, f_dst, w_h_a, cur_f, src_f, w_f);

    // ---- encoder: one fused N=512 GEMM (xl_e | xr_e | xl_p | xr_p) ----
    k_cvt<<<(NN * DI) / 256, 256>>>(x, Ah, Al, NN * DI);
    k_packB_enc<<<(DI * 512) / 256, 256>>>(enc_Wl, enc_Wr);
    {
        dim3 g(4, NN / 64);
        k_gemm3<<<g, 256>>>(Ah, Al, DI, xl_e, xr_e, xl_p, xr_p, 7);
    }
    k_gatherperm<<<(NN * DL) / 256, 256>>>();

    // ---- fused GAT calls ----
    k_gat<DL><<<NN / 8, 256>>>(rp_s, src_s, w_s, xl_e, xr_e, enc_att, enc_b, hi);
    k_gat<DL><<<NN / 8, 256>>>(rp_f, src_f, w_f, xl_p, xr_p, enc_att, enc_b, gg1);
    k_gat<DL><<<NN / 8, 256>>>(rp_s, src_s, w_s, xl_n, xr_n, enc_att, enc_b, gg2);

    // ---- decoder: one fused N=512 GEMM (xl_d | xr_d) ----
    k_cvt<<<(NN * DL) / 256, 256>>>(hi, Ah, Al, NN * DL);
    k_packB_dec<<<(DL * 512) / 256, 256>>>(dec_Wl, dec_Wr);
    {
        dim3 g(4, NN / 64);
        k_gemm3<<<g, 256>>>(Ah, Al, DL, xl_d, xr_d, xl_d, xr_d, 8);
    }
    k_gat<DI><<<NN / 8, 256>>>(rp_s, src_s, w_s, xl_d, xr_d, dec_att, dec_b, h);

    // ---- BN + ELU + L2 norm -> bf16 (fused) ----
    {
        dim3 g(32, 3);
        k_bnstats3<<<g, 256>>>(hi, gg1, gg2);
        dim3 g2(NN / 8, 3);
        k_bnl2<<<g2, 256>>>(hi, gg1, gg2, bn_g, bn_b);
    }

    // ---- losses ----
    k_rec<<<256, 256>>>(x, h);
    k_nce_mma<<<NN / 64, 256, NCE_SMEM>>>();
    k_final<<<1, 1>>>(loss);
}